// round 1
// baseline (speedup 1.0000x reference)
#include <cuda_runtime.h>
#include <math.h>

#define BB    16
#define DIM   384
#define HW    56
#define WS    7
#define NWIN  (BB * 8 * 8)       // 1024
#define NTOK  49
#define ROWS  (NWIN * NTOK)      // 50176
#define HEADS 12
#define HD    32
#define QKVN  (3 * DIM)          // 1152

// Scratch (device globals — no allocation allowed in kernel_launch)
__device__ __align__(128) float g_xw [(size_t)ROWS * DIM];     //  77 MB windows
__device__ __align__(128) float g_qkv[(size_t)ROWS * QKVN];    // 231 MB qkv
__device__ __align__(128) float g_att[(size_t)ROWS * DIM];     //  77 MB attn out
__device__ __align__(128) float g_out[(size_t)ROWS * DIM];     //  77 MB proj out

// ---------------------------------------------------------------------------
// Gather: x [B, D, H, W] -> xw [win*49+t, D], smem tile transpose.
// Block = (d-chunk of 64, spatial row hh, batch b).
// ---------------------------------------------------------------------------
__global__ __launch_bounds__(256) void gather_win(const float* __restrict__ x,
                                                  float* __restrict__ xw) {
    __shared__ float tile[64][57];
    const int dc = blockIdx.x;      // 0..5
    const int hh = blockIdx.y;      // 0..55
    const int b  = blockIdx.z;      // 0..15
    const float* xp = x + (((size_t)b * DIM + dc * 64) * HW + hh) * HW;
    for (int i = threadIdx.x; i < 64 * HW; i += 256) {
        int d = i / HW, w = i % HW;
        tile[d][w] = xp[(size_t)d * HW * HW + w];   // coalesced over w
    }
    __syncthreads();
    const int wh = hh / WS, r = hh % WS;
    for (int i = threadIdx.x; i < 64 * HW; i += 256) {
        int d = i & 63, w = i >> 6;
        int win = b * 64 + wh * 8 + (w / 7);
        int t   = r * 7 + (w % 7);
        xw[(size_t)(win * NTOK + t) * DIM + dc * 64 + d] = tile[d][w]; // coalesced over d
    }
}

// ---------------------------------------------------------------------------
// Scatter: pout [win*49+t, D] -> y [B, D, H, W] (inverse of gather)
// ---------------------------------------------------------------------------
__global__ __launch_bounds__(256) void scatter_win(const float* __restrict__ pout,
                                                   float* __restrict__ y) {
    __shared__ float tile[64][57];
    const int dc = blockIdx.x;
    const int hh = blockIdx.y;
    const int b  = blockIdx.z;
    const int wh = hh / WS, r = hh % WS;
    for (int i = threadIdx.x; i < 64 * HW; i += 256) {
        int d = i & 63, w = i >> 6;
        int win = b * 64 + wh * 8 + (w / 7);
        int t   = r * 7 + (w % 7);
        tile[d][w] = pout[(size_t)(win * NTOK + t) * DIM + dc * 64 + d];
    }
    __syncthreads();
    float* yp = y + (((size_t)b * DIM + dc * 64) * HW + hh) * HW;
    for (int i = threadIdx.x; i < 64 * HW; i += 256) {
        int d = i / HW, w = i % HW;
        yp[(size_t)d * HW * HW + w] = tile[d][w];
    }
}

// ---------------------------------------------------------------------------
// SGEMM: C[M,N] = A[M,K] @ B[K,N] + bias[N]. 128x128x8 tiles, 8x8 per thread.
// Requires M%128==0, N%128==0, K%8==0 (true for all our calls).
// ---------------------------------------------------------------------------
__global__ __launch_bounds__(256) void sgemm_bias(const float* __restrict__ A,
                                                  const float* __restrict__ B,
                                                  const float* __restrict__ bias,
                                                  float* __restrict__ C,
                                                  int M, int N, int K) {
    constexpr int BM = 128, BN = 128, BK = 8;
    __shared__ float As[BK][BM];
    __shared__ float Bs[BK][BN];
    const int tid  = threadIdx.x;
    const int tcol = tid & 15;       // 0..15
    const int trow = tid >> 4;       // 0..15
    const float* Ap = A + (size_t)blockIdx.y * BM * K;
    const float* Bp = B + blockIdx.x * BN;
    const int arow = tid >> 1;            // 0..127
    const int acol = (tid & 1) * 4;       // 0 or 4
    const int brow = tid >> 5;            // 0..7
    const int bcol = (tid & 31) * 4;      // 0..124

    float acc[8][8] = {};
    for (int k0 = 0; k0 < K; k0 += BK) {
        float4 av = *(const float4*)(Ap + (size_t)arow * K + k0 + acol);
        As[acol + 0][arow] = av.x;
        As[acol + 1][arow] = av.y;
        As[acol + 2][arow] = av.z;
        As[acol + 3][arow] = av.w;
        float4 bv = *(const float4*)(Bp + (size_t)(k0 + brow) * N + bcol);
        *(float4*)(&Bs[brow][bcol]) = bv;
        __syncthreads();
#pragma unroll
        for (int kk = 0; kk < BK; kk++) {
            float ar[8], br[8];
#pragma unroll
            for (int i = 0; i < 8; i++) ar[i] = As[kk][trow * 8 + i];
#pragma unroll
            for (int j = 0; j < 8; j++) br[j] = Bs[kk][tcol * 8 + j];
#pragma unroll
            for (int i = 0; i < 8; i++)
#pragma unroll
                for (int j = 0; j < 8; j++)
                    acc[i][j] = fmaf(ar[i], br[j], acc[i][j]);
        }
        __syncthreads();
    }
    float* Cp = C + (size_t)blockIdx.y * BM * N + blockIdx.x * BN;
    const float* bp = bias + blockIdx.x * BN;
#pragma unroll
    for (int i = 0; i < 8; i++) {
        int r = trow * 8 + i;
#pragma unroll
        for (int j = 0; j < 8; j += 4) {
            int c = tcol * 8 + j;
            float4 o;
            o.x = acc[i][j + 0] + bp[c + 0];
            o.y = acc[i][j + 1] + bp[c + 1];
            o.z = acc[i][j + 2] + bp[c + 2];
            o.w = acc[i][j + 3] + bp[c + 3];
            *(float4*)(Cp + (size_t)r * N + c) = o;
        }
    }
}

// ---------------------------------------------------------------------------
// Attention: one block per (window, head). q,k,v 49x32 in smem (zero-padded to
// 56 rows), 4x4 register-tiled score GEMM, per-row softmax, 4x4-tiled P@V.
// ---------------------------------------------------------------------------
__global__ __launch_bounds__(256) void attn_kernel(const float* __restrict__ qkv,
                                                   float* __restrict__ att) {
    const int win = blockIdx.x / HEADS;
    const int h   = blockIdx.x % HEADS;
    __shared__ float sq[56][33];
    __shared__ float sk[56][33];
    __shared__ float sv[56][33];
    __shared__ float sS[56][57];
    const int tid = threadIdx.x;
    const float* base = qkv + (size_t)win * NTOK * QKVN + h * HD;

    for (int i = tid; i < 56 * 32; i += 256) {
        int t = i >> 5, d = i & 31;
        float qv = 0.f, kv = 0.f, vv = 0.f;
        if (t < NTOK) {
            const float* p = base + (size_t)t * QKVN;
            qv = p[d];
            kv = p[DIM + d];
            vv = p[2 * DIM + d];
        }
        sq[t][d] = qv; sk[t][d] = kv; sv[t][d] = vv;
    }
    __syncthreads();

    // Phase 1: S = (q @ k^T) * scale, 14x14 tiles of 4x4
    if (tid < 196) {
        const int it = tid / 14, jt = tid % 14;
        float acc[4][4] = {};
#pragma unroll
        for (int kk = 0; kk < HD; kk++) {
            float aq[4], bk[4];
#pragma unroll
            for (int a = 0; a < 4; a++) aq[a] = sq[it * 4 + a][kk];
#pragma unroll
            for (int b = 0; b < 4; b++) bk[b] = sk[jt * 4 + b][kk];
#pragma unroll
            for (int a = 0; a < 4; a++)
#pragma unroll
                for (int b = 0; b < 4; b++)
                    acc[a][b] = fmaf(aq[a], bk[b], acc[a][b]);
        }
        const float scale = 0.17677669529663687f;  // 1/sqrt(32)
#pragma unroll
        for (int a = 0; a < 4; a++)
#pragma unroll
            for (int b = 0; b < 4; b++)
                sS[it * 4 + a][jt * 4 + b] = acc[a][b] * scale;
    }
    __syncthreads();

    // Softmax per valid row (j < 49 only; padded cols never read in phase 2)
    if (tid < NTOK) {
        float m = -1e30f;
        for (int j = 0; j < NTOK; j++) m = fmaxf(m, sS[tid][j]);
        float s = 0.f;
        for (int j = 0; j < NTOK; j++) {
            float e = expf(sS[tid][j] - m);
            sS[tid][j] = e;
            s += e;
        }
        float inv = 1.0f / s;
        for (int j = 0; j < NTOK; j++) sS[tid][j] *= inv;
    }
    __syncthreads();

    // Phase 2: O[56x32] = P[56x49] @ V[49x32], 14x8 tiles of 4x4
    if (tid < 112) {
        const int it = tid / 8, jt = tid % 8;
        float acc[4][4] = {};
        for (int j = 0; j < NTOK; j++) {
            float ap[4], bv[4];
#pragma unroll
            for (int a = 0; a < 4; a++) ap[a] = sS[it * 4 + a][j];
#pragma unroll
            for (int b = 0; b < 4; b++) bv[b] = sv[j][jt * 4 + b];
#pragma unroll
            for (int a = 0; a < 4; a++)
#pragma unroll
                for (int b = 0; b < 4; b++)
                    acc[a][b] = fmaf(ap[a], bv[b], acc[a][b]);
        }
#pragma unroll
        for (int a = 0; a < 4; a++) {
            int row = it * 4 + a;
            if (row < NTOK) {
                float* op = att + (size_t)(win * NTOK + row) * DIM + h * HD + jt * 4;
#pragma unroll
                for (int b = 0; b < 4; b++) op[b] = acc[a][b];
            }
        }
    }
}

// ---------------------------------------------------------------------------
extern "C" void kernel_launch(void* const* d_in, const int* in_sizes, int n_in,
                              void* d_out, int out_size) {
    const float* x     = (const float*)d_in[0];
    const float* Wqkv  = (const float*)d_in[1];
    const float* bqkv  = (const float*)d_in[2];
    const float* Wproj = (const float*)d_in[3];
    const float* bproj = (const float*)d_in[4];
    float* out = (float*)d_out;

    float *xw, *qkv, *att, *po;
    cudaGetSymbolAddress((void**)&xw,  g_xw);
    cudaGetSymbolAddress((void**)&qkv, g_qkv);
    cudaGetSymbolAddress((void**)&att, g_att);
    cudaGetSymbolAddress((void**)&po,  g_out);

    // 1) window gather
    gather_win<<<dim3(6, HW, BB), 256>>>(x, xw);
    // 2) QKV GEMM: [50176,384] @ [384,1152] + bqkv
    sgemm_bias<<<dim3(QKVN / 128, ROWS / 128), 256>>>(xw, Wqkv, bqkv, qkv,
                                                      ROWS, QKVN, DIM);
    // 3) attention per (window, head)
    attn_kernel<<<NWIN * HEADS, 256>>>(qkv, att);
    // 4) proj GEMM: [50176,384] @ [384,384] + bproj
    sgemm_bias<<<dim3(DIM / 128, ROWS / 128), 256>>>(att, Wproj, bproj, po,
                                                     ROWS, DIM, DIM);
    // 5) scatter back to NCHW
    scatter_win<<<dim3(6, HW, BB), 256>>>(po, out);
}

// round 3
// speedup vs baseline: 3.0397x; 3.0397x over previous
#include <cuda_runtime.h>
#include <cuda_fp16.h>
#include <math.h>
#include <stdint.h>

#define BB    16
#define DIM   384
#define HW    56
#define WS    7
#define NWIN  (BB * 8 * 8)       // 1024
#define NTOK  49
#define ROWS  (NWIN * NTOK)      // 50176
#define HEADS 12
#define HD    32
#define QKVN  (3 * DIM)          // 1152

// Scratch (device globals — no allocation allowed in kernel_launch)
__device__ __align__(128) __half g_xwh [(size_t)ROWS * DIM];    // gathered x, half
__device__ __align__(128) float  g_qkv [(size_t)ROWS * QKVN];   // qkv, f32
__device__ __align__(128) __half g_atth[(size_t)ROWS * DIM];    // attn out, half
__device__ __align__(128) float  g_out [(size_t)ROWS * DIM];    // proj out, f32
__device__ __align__(128) __half g_wt  [(size_t)QKVN * DIM];    // Wqkv^T half
__device__ __align__(128) __half g_wtp [(size_t)DIM * DIM];     // Wproj^T half

// ---------------------------------------------------------------------------
// PTX helpers
// ---------------------------------------------------------------------------
__device__ __forceinline__ uint32_t smem_u32(const void* p) {
    uint32_t a;
    asm("{ .reg .u64 t; cvta.to.shared.u64 t, %1; cvt.u32.u64 %0, t; }"
        : "=r"(a) : "l"(p));
    return a;
}

__device__ __forceinline__ void cp16(uint32_t dst, const void* src) {
    asm volatile("cp.async.cg.shared.global [%0], [%1], 16;"
                 :: "r"(dst), "l"(src));
}

__device__ __forceinline__ void ldsm_x4(uint32_t* r, uint32_t addr) {
    asm volatile("ldmatrix.sync.aligned.m8n8.x4.shared.b16 {%0,%1,%2,%3}, [%4];"
                 : "=r"(r[0]), "=r"(r[1]), "=r"(r[2]), "=r"(r[3]) : "r"(addr));
}

__device__ __forceinline__ void ldsm_x2(uint32_t* r, uint32_t addr) {
    asm volatile("ldmatrix.sync.aligned.m8n8.x2.shared.b16 {%0,%1}, [%2];"
                 : "=r"(r[0]), "=r"(r[1]) : "r"(addr));
}

__device__ __forceinline__ void mma16816(float* c, const uint32_t* a, const uint32_t* b) {
    asm volatile(
        "mma.sync.aligned.m16n8k16.row.col.f32.f16.f16.f32 "
        "{%0,%1,%2,%3}, {%4,%5,%6,%7}, {%8,%9}, {%0,%1,%2,%3};"
        : "+f"(c[0]), "+f"(c[1]), "+f"(c[2]), "+f"(c[3])
        : "r"(a[0]), "r"(a[1]), "r"(a[2]), "r"(a[3]), "r"(b[0]), "r"(b[1]));
}

// ---------------------------------------------------------------------------
// Gather: x [B, D, H, W] -> xwh [win*49+t, D] (half)
// ---------------------------------------------------------------------------
__global__ __launch_bounds__(256) void gather_win(const float* __restrict__ x,
                                                  __half* __restrict__ xw) {
    __shared__ float tile[64][57];
    const int dc = blockIdx.x;
    const int hh = blockIdx.y;
    const int b  = blockIdx.z;
    const float* xp = x + (((size_t)b * DIM + dc * 64) * HW + hh) * HW;
    for (int i = threadIdx.x; i < 64 * HW; i += 256) {
        int d = i / HW, w = i % HW;
        tile[d][w] = xp[(size_t)d * HW * HW + w];
    }
    __syncthreads();
    const int wh = hh / WS, r = hh % WS;
    for (int i = threadIdx.x; i < 64 * HW; i += 256) {
        int d = i & 63, w = i >> 6;
        int win = b * 64 + wh * 8 + (w / 7);
        int t   = r * 7 + (w % 7);
        xw[(size_t)(win * NTOK + t) * DIM + dc * 64 + d] = __float2half(tile[d][w]);
    }
}

// ---------------------------------------------------------------------------
// Scatter: pout [win*49+t, D] (f32) -> y [B, D, H, W]
// ---------------------------------------------------------------------------
__global__ __launch_bounds__(256) void scatter_win(const float* __restrict__ pout,
                                                   float* __restrict__ y) {
    __shared__ float tile[64][57];
    const int dc = blockIdx.x;
    const int hh = blockIdx.y;
    const int b  = blockIdx.z;
    const int wh = hh / WS, r = hh % WS;
    for (int i = threadIdx.x; i < 64 * HW; i += 256) {
        int d = i & 63, w = i >> 6;
        int win = b * 64 + wh * 8 + (w / 7);
        int t   = r * 7 + (w % 7);
        tile[d][w] = pout[(size_t)(win * NTOK + t) * DIM + dc * 64 + d];
    }
    __syncthreads();
    float* yp = y + (((size_t)b * DIM + dc * 64) * HW + hh) * HW;
    for (int i = threadIdx.x; i < 64 * HW; i += 256) {
        int d = i / HW, w = i % HW;
        yp[(size_t)d * HW * HW + w] = tile[d][w];
    }
}

// ---------------------------------------------------------------------------
// Weight transpose to half: W [K, N] f32 -> Wt [N, K] half
// ---------------------------------------------------------------------------
__global__ void transpose_w(const float* __restrict__ W, __half* __restrict__ Wt,
                            int K, int N) {
    __shared__ float t[32][33];
    int n0 = blockIdx.x * 32, k0 = blockIdx.y * 32;
    int x = threadIdx.x, y = threadIdx.y;
    for (int i = y; i < 32; i += 8)
        t[i][x] = W[(size_t)(k0 + i) * N + n0 + x];
    __syncthreads();
    for (int i = y; i < 32; i += 8)
        Wt[(size_t)(n0 + i) * K + k0 + x] = __float2half(t[x][i]);
}

// ---------------------------------------------------------------------------
// HGEMM (mma.sync, fp16 in / fp32 acc): C[M,N] = A[M,K] @ Bt[N,K]^T + bias[N]
// 128x128 tile, BK=64, SW128 swizzle, 2-stage cp.async pipeline, 8 warps
// each computing 64x32. Requires M%128==0, N%128==0, K%64==0.
// ---------------------------------------------------------------------------
#define STAGE_B 32768   // A(16KB) + B(16KB) per stage

__global__ __launch_bounds__(256) void hgemm(const __half* __restrict__ A,
                                             const __half* __restrict__ Bt,
                                             const float* __restrict__ bias,
                                             float* __restrict__ C,
                                             int M, int N, int K) {
    extern __shared__ char dsm[];
    const uint32_t sb = (smem_u32(dsm) + 1023u) & ~1023u;

    const int tid  = threadIdx.x;
    const int wid  = tid >> 5, lane = tid & 31;
    const int wm   = wid & 1;         // 0..1 -> 64-row block
    const int wn   = wid >> 1;        // 0..3 -> 32-col block

    const __half* Ap = A  + (size_t)blockIdx.y * 128 * K;
    const __half* Bp = Bt + (size_t)blockIdx.x * 128 * K;
    const int NC = K >> 6;            // chunks of BK=64

    // cp.async mapping: 2048 16B-segments per stage (1024 A + 1024 B), 8/thread
    // seg -> row = seg>>3, j = seg&7 ; swizzled chunk = j ^ (row&7)
    auto load_stage = [&](int stage, int k0) {
        const uint32_t sA = sb + stage * STAGE_B, sB = sA + 16384;
#pragma unroll
        for (int i = 0; i < 4; i++) {
            int seg = tid + 256 * i;
            int row = seg >> 3, j = seg & 7;
            uint32_t dst = (uint32_t)(row * 128 + ((j ^ (row & 7)) << 4));
            cp16(sA + dst, Ap + (size_t)row * K + k0 + j * 8);
            cp16(sB + dst, Bp + (size_t)row * K + k0 + j * 8);
        }
        asm volatile("cp.async.commit_group;" ::: "memory");
    };

    load_stage(0, 0);

    float acc[4][4][4] = {};
    // ldmatrix lane addressing (within tile):
    //   A rows: lane&15 ; chunk base += lane>>4
    //   B rows: lane&7  ; chunk base += (lane>>3)&1
    const int arow = wm * 64 + (lane & 15);
    const int ac   = lane >> 4;
    const int brow = wn * 32 + (lane & 7);
    const int bc   = (lane >> 3) & 1;
    const int arx  = arow & 7, brx = brow & 7;

    for (int c = 0; c < NC; c++) {
        const int s = c & 1;
        if (c + 1 < NC) {
            load_stage((c + 1) & 1, (c + 1) * 64);
            asm volatile("cp.async.wait_group 1;" ::: "memory");
        } else {
            asm volatile("cp.async.wait_group 0;" ::: "memory");
        }
        __syncthreads();

        const uint32_t sA = sb + s * STAGE_B, sB = sA + 16384;
#pragma unroll
        for (int ks = 0; ks < 4; ks++) {
            uint32_t af[4][4], bf[4][2];
#pragma unroll
            for (int mt = 0; mt < 4; mt++) {
                int row = arow + mt * 16;
                uint32_t addr = sA + (uint32_t)(row * 128 +
                                (((ks * 2 + ac) ^ arx) << 4));
                ldsm_x4(af[mt], addr);
            }
#pragma unroll
            for (int nt = 0; nt < 4; nt++) {
                int row = brow + nt * 8;
                uint32_t addr = sB + (uint32_t)(row * 128 +
                                (((ks * 2 + bc) ^ brx) << 4));
                ldsm_x2(bf[nt], addr);
            }
#pragma unroll
            for (int mt = 0; mt < 4; mt++)
#pragma unroll
                for (int nt = 0; nt < 4; nt++)
                    mma16816(acc[mt][nt], af[mt], bf[nt]);
        }
        __syncthreads();
    }

    // Epilogue: c0,c1 at (row, col..col+1), c2,c3 at (row+8, col..col+1)
    const int r0 = blockIdx.y * 128 + wm * 64 + (lane >> 2);
    const int c0 = blockIdx.x * 128 + wn * 32 + (lane & 3) * 2;
#pragma unroll
    for (int mt = 0; mt < 4; mt++) {
#pragma unroll
        for (int nt = 0; nt < 4; nt++) {
            int r = r0 + mt * 16, cc = c0 + nt * 8;
            float b0 = bias[cc], b1 = bias[cc + 1];
            float2 o0 = { acc[mt][nt][0] + b0, acc[mt][nt][1] + b1 };
            float2 o1 = { acc[mt][nt][2] + b0, acc[mt][nt][3] + b1 };
            *(float2*)(C + (size_t)r * N + cc)       = o0;
            *(float2*)(C + (size_t)(r + 8) * N + cc) = o1;
        }
    }
}

// ---------------------------------------------------------------------------
// Attention: one block per (window, head). Reads f32 qkv, writes half att.
// ---------------------------------------------------------------------------
__global__ __launch_bounds__(256) void attn_kernel(const float* __restrict__ qkv,
                                                   __half* __restrict__ att) {
    const int win = blockIdx.x / HEADS;
    const int h   = blockIdx.x % HEADS;
    __shared__ float sq[56][33];
    __shared__ float sk[56][33];
    __shared__ float sv[56][33];
    __shared__ float sS[56][57];
    const int tid = threadIdx.x;
    const float* base = qkv + (size_t)win * NTOK * QKVN + h * HD;

    for (int i = tid; i < 56 * 32; i += 256) {
        int t = i >> 5, d = i & 31;
        float qv = 0.f, kv = 0.f, vv = 0.f;
        if (t < NTOK) {
            const float* p = base + (size_t)t * QKVN;
            qv = p[d];
            kv = p[DIM + d];
            vv = p[2 * DIM + d];
        }
        sq[t][d] = qv; sk[t][d] = kv; sv[t][d] = vv;
    }
    __syncthreads();

    if (tid < 196) {
        const int it = tid / 14, jt = tid % 14;
        float acc[4][4] = {};
#pragma unroll
        for (int kk = 0; kk < HD; kk++) {
            float aq[4], bk[4];
#pragma unroll
            for (int a = 0; a < 4; a++) aq[a] = sq[it * 4 + a][kk];
#pragma unroll
            for (int b = 0; b < 4; b++) bk[b] = sk[jt * 4 + b][kk];
#pragma unroll
            for (int a = 0; a < 4; a++)
#pragma unroll
                for (int b = 0; b < 4; b++)
                    acc[a][b] = fmaf(aq[a], bk[b], acc[a][b]);
        }
        const float scale = 0.17677669529663687f;
#pragma unroll
        for (int a = 0; a < 4; a++)
#pragma unroll
            for (int b = 0; b < 4; b++)
                sS[it * 4 + a][jt * 4 + b] = acc[a][b] * scale;
    }
    __syncthreads();

    if (tid < NTOK) {
        float m = -1e30f;
        for (int j = 0; j < NTOK; j++) m = fmaxf(m, sS[tid][j]);
        float s = 0.f;
        for (int j = 0; j < NTOK; j++) {
            float e = expf(sS[tid][j] - m);
            sS[tid][j] = e;
            s += e;
        }
        float inv = 1.0f / s;
        for (int j = 0; j < NTOK; j++) sS[tid][j] *= inv;
    }
    __syncthreads();

    if (tid < 112) {
        const int it = tid / 8, jt = tid % 8;
        float acc[4][4] = {};
        for (int j = 0; j < NTOK; j++) {
            float ap[4], bv[4];
#pragma unroll
            for (int a = 0; a < 4; a++) ap[a] = sS[it * 4 + a][j];
#pragma unroll
            for (int b = 0; b < 4; b++) bv[b] = sv[j][jt * 4 + b];
#pragma unroll
            for (int a = 0; a < 4; a++)
#pragma unroll
                for (int b = 0; b < 4; b++)
                    acc[a][b] = fmaf(ap[a], bv[b], acc[a][b]);
        }
#pragma unroll
        for (int a = 0; a < 4; a++) {
            int row = it * 4 + a;
            if (row < NTOK) {
                __half* op = att + (size_t)(win * NTOK + row) * DIM + h * HD + jt * 4;
#pragma unroll
                for (int b = 0; b < 4; b++) op[b] = __float2half(acc[a][b]);
            }
        }
    }
}

// ---------------------------------------------------------------------------
extern "C" void kernel_launch(void* const* d_in, const int* in_sizes, int n_in,
                              void* d_out, int out_size) {
    const float* x     = (const float*)d_in[0];
    const float* Wqkv  = (const float*)d_in[1];
    const float* bqkv  = (const float*)d_in[2];
    const float* Wproj = (const float*)d_in[3];
    const float* bproj = (const float*)d_in[4];
    float* out = (float*)d_out;

    __half *xwh, *atth, *wt, *wtp;
    float *qkv, *po;
    cudaGetSymbolAddress((void**)&xwh,  g_xwh);
    cudaGetSymbolAddress((void**)&qkv,  g_qkv);
    cudaGetSymbolAddress((void**)&atth, g_atth);
    cudaGetSymbolAddress((void**)&po,   g_out);
    cudaGetSymbolAddress((void**)&wt,   g_wt);
    cudaGetSymbolAddress((void**)&wtp,  g_wtp);

    const int smem_bytes = 2 * STAGE_B + 1024;
    cudaFuncSetAttribute(hgemm, cudaFuncAttributeMaxDynamicSharedMemorySize,
                         smem_bytes);

    // 0) transpose weights to half (tiny)
    transpose_w<<<dim3(QKVN / 32, DIM / 32), dim3(32, 8)>>>(Wqkv, wt, DIM, QKVN);
    transpose_w<<<dim3(DIM / 32, DIM / 32), dim3(32, 8)>>>(Wproj, wtp, DIM, DIM);
    // 1) window gather (-> half)
    gather_win<<<dim3(6, HW, BB), 256>>>(x, xwh);
    // 2) QKV GEMM (fp16 mma, f32 acc): [50176,384] @ [384,1152] + bqkv
    hgemm<<<dim3(QKVN / 128, ROWS / 128), 256, smem_bytes>>>(xwh, wt, bqkv, qkv,
                                                             ROWS, QKVN, DIM);
    // 3) attention per (window, head), f32 in -> half out
    attn_kernel<<<NWIN * HEADS, 256>>>(qkv, atth);
    // 4) proj GEMM: [50176,384] @ [384,384] + bproj
    hgemm<<<dim3(DIM / 128, ROWS / 128), 256, smem_bytes>>>(atth, wtp, bproj, po,
                                                            ROWS, DIM, DIM);
    // 5) scatter back to NCHW
    scatter_win<<<dim3(6, HW, BB), 256>>>(po, out);
}

// round 6
// speedup vs baseline: 5.0506x; 1.6616x over previous
#include <cuda_runtime.h>
#include <cuda_fp16.h>
#include <math.h>
#include <stdint.h>

#define BB    16
#define DIM   384
#define HW    56
#define WS    7
#define NWIN  (BB * 8 * 8)       // 1024
#define NTOK  49
#define ROWS  (NWIN * NTOK)      // 50176
#define HEADS 12
#define HD    32
#define QKVN  (3 * DIM)          // 1152

// Scratch (device globals — no allocation allowed in kernel_launch)
__device__ __align__(128) __half g_xwh [(size_t)ROWS * DIM];
__device__ __align__(128) __half g_qkvh[(size_t)ROWS * QKVN];
__device__ __align__(128) __half g_atth[(size_t)ROWS * DIM];
__device__ __align__(128) float  g_out [(size_t)ROWS * DIM];
__device__ __align__(128) __half g_wt  [(size_t)QKVN * DIM];
__device__ __align__(128) __half g_wtp [(size_t)DIM * DIM];

// ---------------------------------------------------------------------------
// PTX helpers
// ---------------------------------------------------------------------------
__device__ __forceinline__ uint32_t smem_u32(const void* p) {
    uint32_t a;
    asm("{ .reg .u64 t; cvta.to.shared.u64 t, %1; cvt.u32.u64 %0, t; }"
        : "=r"(a) : "l"(p));
    return a;
}
__device__ __forceinline__ void cp16(uint32_t dst, const void* src) {
    asm volatile("cp.async.cg.shared.global [%0], [%1], 16;"
                 :: "r"(dst), "l"(src));
}
__device__ __forceinline__ void ldsm_x4(uint32_t* r, uint32_t addr) {
    asm volatile("ldmatrix.sync.aligned.m8n8.x4.shared.b16 {%0,%1,%2,%3}, [%4];"
                 : "=r"(r[0]), "=r"(r[1]), "=r"(r[2]), "=r"(r[3]) : "r"(addr));
}
__device__ __forceinline__ void ldsm_x2(uint32_t* r, uint32_t addr) {
    asm volatile("ldmatrix.sync.aligned.m8n8.x2.shared.b16 {%0,%1}, [%2];"
                 : "=r"(r[0]), "=r"(r[1]) : "r"(addr));
}
__device__ __forceinline__ void ldsm_x2t(uint32_t* r, uint32_t addr) {
    asm volatile("ldmatrix.sync.aligned.m8n8.x2.trans.shared.b16 {%0,%1}, [%2];"
                 : "=r"(r[0]), "=r"(r[1]) : "r"(addr));
}
__device__ __forceinline__ void mma16816(float* c, const uint32_t* a, const uint32_t* b) {
    asm volatile(
        "mma.sync.aligned.m16n8k16.row.col.f32.f16.f16.f32 "
        "{%0,%1,%2,%3}, {%4,%5,%6,%7}, {%8,%9}, {%0,%1,%2,%3};"
        : "+f"(c[0]), "+f"(c[1]), "+f"(c[2]), "+f"(c[3])
        : "r"(a[0]), "r"(a[1]), "r"(a[2]), "r"(a[3]), "r"(b[0]), "r"(b[1]));
}
// pack two floats into one uint32 holding a half2 (FULL 32 bits — the round-4
// bug was extracting only __half2_raw::x, a 16-bit field)
__device__ __forceinline__ uint32_t pack_h2(float a, float b) {
    __half2 h = __floats2half2_rn(a, b);
    return *reinterpret_cast<uint32_t*>(&h);
}

// ---------------------------------------------------------------------------
// Gather: x [B, D, H, W] -> xwh [win*49+t, D] (half)
// ---------------------------------------------------------------------------
__global__ __launch_bounds__(256) void gather_win(const float* __restrict__ x,
                                                  __half* __restrict__ xw) {
    __shared__ float tile[64][57];
    const int dc = blockIdx.x;
    const int hh = blockIdx.y;
    const int b  = blockIdx.z;
    const float* xp = x + (((size_t)b * DIM + dc * 64) * HW + hh) * HW;
    for (int i = threadIdx.x; i < 64 * HW; i += 256) {
        int d = i / HW, w = i % HW;
        tile[d][w] = xp[(size_t)d * HW * HW + w];
    }
    __syncthreads();
    const int wh = hh / WS, r = hh % WS;
    for (int i = threadIdx.x; i < 64 * HW; i += 256) {
        int d = i & 63, w = i >> 6;
        int win = b * 64 + wh * 8 + (w / 7);
        int t   = r * 7 + (w % 7);
        xw[(size_t)(win * NTOK + t) * DIM + dc * 64 + d] = __float2half(tile[d][w]);
    }
}

// ---------------------------------------------------------------------------
// Scatter: pout [win*49+t, D] (f32) -> y [B, D, H, W]
// ---------------------------------------------------------------------------
__global__ __launch_bounds__(256) void scatter_win(const float* __restrict__ pout,
                                                   float* __restrict__ y) {
    __shared__ float tile[64][57];
    const int dc = blockIdx.x;
    const int hh = blockIdx.y;
    const int b  = blockIdx.z;
    const int wh = hh / WS, r = hh % WS;
    for (int i = threadIdx.x; i < 64 * HW; i += 256) {
        int d = i & 63, w = i >> 6;
        int win = b * 64 + wh * 8 + (w / 7);
        int t   = r * 7 + (w % 7);
        tile[d][w] = pout[(size_t)(win * NTOK + t) * DIM + dc * 64 + d];
    }
    __syncthreads();
    float* yp = y + (((size_t)b * DIM + dc * 64) * HW + hh) * HW;
    for (int i = threadIdx.x; i < 64 * HW; i += 256) {
        int d = i / HW, w = i % HW;
        yp[(size_t)d * HW * HW + w] = tile[d][w];
    }
}

// ---------------------------------------------------------------------------
// Weight transpose to half: W [K, N] f32 -> Wt [N, K] half
// ---------------------------------------------------------------------------
__global__ void transpose_w(const float* __restrict__ W, __half* __restrict__ Wt,
                            int K, int N) {
    __shared__ float t[32][33];
    int n0 = blockIdx.x * 32, k0 = blockIdx.y * 32;
    int x = threadIdx.x, y = threadIdx.y;
    for (int i = y; i < 32; i += 8)
        t[i][x] = W[(size_t)(k0 + i) * N + n0 + x];
    __syncthreads();
    for (int i = y; i < 32; i += 8)
        Wt[(size_t)(n0 + i) * K + k0 + x] = __float2half(t[x][i]);
}

// ---------------------------------------------------------------------------
// HGEMM: C[M,N] = A[M,K] @ Bt[N,K]^T + bias[N]; OutT = float or __half
// ---------------------------------------------------------------------------
#define STAGE_B 32768

template<typename OutT>
__global__ __launch_bounds__(256) void hgemm(const __half* __restrict__ A,
                                             const __half* __restrict__ Bt,
                                             const float* __restrict__ bias,
                                             OutT* __restrict__ C,
                                             int M, int N, int K) {
    extern __shared__ char dsm[];
    const uint32_t sb = (smem_u32(dsm) + 1023u) & ~1023u;

    const int tid  = threadIdx.x;
    const int wid  = tid >> 5, lane = tid & 31;
    const int wm   = wid & 1;
    const int wn   = wid >> 1;

    const __half* Ap = A  + (size_t)blockIdx.y * 128 * K;
    const __half* Bp = Bt + (size_t)blockIdx.x * 128 * K;
    const int NC = K >> 6;

    auto load_stage = [&](int stage, int k0) {
        const uint32_t sA = sb + stage * STAGE_B, sB = sA + 16384;
#pragma unroll
        for (int i = 0; i < 4; i++) {
            int seg = tid + 256 * i;
            int row = seg >> 3, j = seg & 7;
            uint32_t dst = (uint32_t)(row * 128 + ((j ^ (row & 7)) << 4));
            cp16(sA + dst, Ap + (size_t)row * K + k0 + j * 8);
            cp16(sB + dst, Bp + (size_t)row * K + k0 + j * 8);
        }
        asm volatile("cp.async.commit_group;" ::: "memory");
    };

    load_stage(0, 0);

    float acc[4][4][4] = {};
    const int arow = wm * 64 + (lane & 15);
    const int ac   = lane >> 4;
    const int brow = wn * 32 + (lane & 7);
    const int bc   = (lane >> 3) & 1;
    const int arx  = arow & 7, brx = brow & 7;

    for (int c = 0; c < NC; c++) {
        const int s = c & 1;
        if (c + 1 < NC) {
            load_stage((c + 1) & 1, (c + 1) * 64);
            asm volatile("cp.async.wait_group 1;" ::: "memory");
        } else {
            asm volatile("cp.async.wait_group 0;" ::: "memory");
        }
        __syncthreads();

        const uint32_t sA = sb + s * STAGE_B, sB = sA + 16384;
#pragma unroll
        for (int ks = 0; ks < 4; ks++) {
            uint32_t af[4][4], bf[4][2];
#pragma unroll
            for (int mt = 0; mt < 4; mt++) {
                int row = arow + mt * 16;
                uint32_t addr = sA + (uint32_t)(row * 128 +
                                (((ks * 2 + ac) ^ arx) << 4));
                ldsm_x4(af[mt], addr);
            }
#pragma unroll
            for (int nt = 0; nt < 4; nt++) {
                int row = brow + nt * 8;
                uint32_t addr = sB + (uint32_t)(row * 128 +
                                (((ks * 2 + bc) ^ brx) << 4));
                ldsm_x2(bf[nt], addr);
            }
#pragma unroll
            for (int mt = 0; mt < 4; mt++)
#pragma unroll
                for (int nt = 0; nt < 4; nt++)
                    mma16816(acc[mt][nt], af[mt], bf[nt]);
        }
        __syncthreads();
    }

    const int r0 = blockIdx.y * 128 + wm * 64 + (lane >> 2);
    const int c0 = blockIdx.x * 128 + wn * 32 + (lane & 3) * 2;
#pragma unroll
    for (int mt = 0; mt < 4; mt++) {
#pragma unroll
        for (int nt = 0; nt < 4; nt++) {
            int r = r0 + mt * 16, cc = c0 + nt * 8;
            float b0 = bias[cc], b1 = bias[cc + 1];
            float v00 = acc[mt][nt][0] + b0, v01 = acc[mt][nt][1] + b1;
            float v10 = acc[mt][nt][2] + b0, v11 = acc[mt][nt][3] + b1;
            if constexpr (sizeof(OutT) == 2) {
                *(__half2*)((__half*)C + (size_t)r * N + cc)       = __floats2half2_rn(v00, v01);
                *(__half2*)((__half*)C + (size_t)(r + 8) * N + cc) = __floats2half2_rn(v10, v11);
            } else {
                *(float2*)((float*)C + (size_t)r * N + cc)       = make_float2(v00, v01);
                *(float2*)((float*)C + (size_t)(r + 8) * N + cc) = make_float2(v10, v11);
            }
        }
    }
}

// ---------------------------------------------------------------------------
// Tensor-core attention: one warp per (window, head).
// q/k/v staged to smem: 64 rows x 32 half, row stride 80B (conflict-free).
// S = Q K^T (m16n8k16), masked softmax in registers, O = P V.
// ---------------------------------------------------------------------------
#define AW_BYTES (3 * 64 * 80)   // per-warp smem: q, k, v

__global__ __launch_bounds__(128) void attn_mma(const __half* __restrict__ qkv,
                                                __half* __restrict__ att) {
    extern __shared__ char sm[];
    const int warp = threadIdx.x >> 5, lane = threadIdx.x & 31;
    const int pairid = blockIdx.x * 4 + warp;
    const int win = pairid / HEADS, h = pairid % HEADS;

    char* smp = sm + warp * AW_BYTES;
    const uint32_t base = smem_u32(smp);
    const uint32_t sq = base, sk = base + 5120, sv = base + 10240;

    const __half* qp = qkv + (size_t)win * NTOK * QKVN + h * HD;

    // stage q,k,v (49 rows x 64B each) via cp.async
#pragma unroll
    for (int m = 0; m < 3; m++) {
        const uint32_t dstb = base + m * 5120;
        const __half* src = qp + m * DIM;
        for (int i = lane; i < 196; i += 32) {
            int t = i >> 2, seg = i & 3;
            cp16(dstb + (uint32_t)(t * 80 + seg * 16), src + (size_t)t * QKVN + seg * 8);
        }
    }
    asm volatile("cp.async.commit_group;" ::: "memory");
    // zero pad rows 49..63 of q,k,v
    const float4 z4 = make_float4(0.f, 0.f, 0.f, 0.f);
    for (int i = lane; i < 225; i += 32) {
        int m = i / 75, rem = i % 75;
        int row = 49 + rem / 5, seg = rem % 5;
        *(float4*)(smp + m * 5120 + row * 80 + seg * 16) = z4;
    }
    asm volatile("cp.async.wait_group 0;" ::: "memory");
    __syncwarp();

    const int r   = lane >> 2;
    const int cpr = lane & 3;

    // Hoisted K fragments (B operand of S): kb[nt][ks][2]
    uint32_t kb[7][2][2];
#pragma unroll
    for (int nt = 0; nt < 7; nt++)
#pragma unroll
        for (int ks = 0; ks < 2; ks++) {
            uint32_t addr = sk + (uint32_t)((nt * 8 + (lane & 7)) * 80 +
                            (ks * 2 + ((lane >> 3) & 1)) * 16);
            ldsm_x2(kb[nt][ks], addr);
        }
    // Hoisted V fragments (B operand of O, via trans): vb[ks][nd][2]
    uint32_t vb[4][4][2];
#pragma unroll
    for (int ks = 0; ks < 4; ks++)
#pragma unroll
        for (int nd = 0; nd < 4; nd++) {
            uint32_t addr = sv + (uint32_t)((ks * 16 + (lane & 15)) * 80 + nd * 16);
            ldsm_x2t(vb[ks][nd], addr);
        }

    const float CSC = 0.25506153f;  // (1/sqrt(32)) * log2(e)

#pragma unroll
    for (int mt = 0; mt < 4; mt++) {
        uint32_t qa[2][4];
#pragma unroll
        for (int ks = 0; ks < 2; ks++) {
            uint32_t addr = sq + (uint32_t)((mt * 16 + (lane & 15)) * 80 +
                            (ks * 2 + (lane >> 4)) * 16);
            ldsm_x4(qa[ks], addr);
        }
        float s[7][4] = {};
#pragma unroll
        for (int nt = 0; nt < 7; nt++) {
            mma16816(s[nt], qa[0], kb[nt][0]);
            mma16816(s[nt], qa[1], kb[nt][1]);
        }
        // scale (log2-domain) + mask cols >= 49 (tile nt=6 holds cols 48..55)
#pragma unroll
        for (int nt = 0; nt < 7; nt++)
#pragma unroll
            for (int j = 0; j < 4; j++) s[nt][j] *= CSC;
        if (cpr != 0) { s[6][0] = s[6][1] = s[6][2] = s[6][3] = -1e30f; }
        else          { s[6][1] = s[6][3] = -1e30f; }

        // rowwise max over the 4-lane group
        float mA = -1e30f, mB = -1e30f;
#pragma unroll
        for (int nt = 0; nt < 7; nt++) {
            mA = fmaxf(mA, fmaxf(s[nt][0], s[nt][1]));
            mB = fmaxf(mB, fmaxf(s[nt][2], s[nt][3]));
        }
        mA = fmaxf(mA, __shfl_xor_sync(0xffffffffu, mA, 1));
        mA = fmaxf(mA, __shfl_xor_sync(0xffffffffu, mA, 2));
        mB = fmaxf(mB, __shfl_xor_sync(0xffffffffu, mB, 1));
        mB = fmaxf(mB, __shfl_xor_sync(0xffffffffu, mB, 2));

        float sumA = 0.f, sumB = 0.f;
#pragma unroll
        for (int nt = 0; nt < 7; nt++) {
            s[nt][0] = exp2f(s[nt][0] - mA);
            s[nt][1] = exp2f(s[nt][1] - mA);
            s[nt][2] = exp2f(s[nt][2] - mB);
            s[nt][3] = exp2f(s[nt][3] - mB);
            sumA += s[nt][0] + s[nt][1];
            sumB += s[nt][2] + s[nt][3];
        }
        sumA += __shfl_xor_sync(0xffffffffu, sumA, 1);
        sumA += __shfl_xor_sync(0xffffffffu, sumA, 2);
        sumB += __shfl_xor_sync(0xffffffffu, sumB, 1);
        sumB += __shfl_xor_sync(0xffffffffu, sumB, 2);
        const float invA = 1.0f / sumA, invB = 1.0f / sumB;

        // convert P to A-operand fragments: pa[ks][4]
        uint32_t pa[4][4];
#pragma unroll
        for (int ks = 0; ks < 4; ks++) {
            int nt0 = 2 * ks, nt1 = 2 * ks + 1;
            pa[ks][0] = pack_h2(s[nt0][0] * invA, s[nt0][1] * invA);
            pa[ks][1] = pack_h2(s[nt0][2] * invB, s[nt0][3] * invB);
            if (nt1 < 7) {
                pa[ks][2] = pack_h2(s[nt1][0] * invA, s[nt1][1] * invA);
                pa[ks][3] = pack_h2(s[nt1][2] * invB, s[nt1][3] * invB);
            } else {
                pa[ks][2] = 0u; pa[ks][3] = 0u;
            }
        }

        float o[4][4] = {};
#pragma unroll
        for (int ks = 0; ks < 4; ks++)
#pragma unroll
            for (int nd = 0; nd < 4; nd++)
                mma16816(o[nd], pa[ks], vb[ks][nd]);

        // store O rows (mt*16 + r) and (+8), cols nd*8 + cpr*2
        const int rowA = mt * 16 + r;
        const int rowB = rowA + 8;
#pragma unroll
        for (int nd = 0; nd < 4; nd++) {
            int col = h * HD + nd * 8 + cpr * 2;
            if (rowA < NTOK)
                *(__half2*)(att + (size_t)(win * NTOK + rowA) * DIM + col) =
                    __floats2half2_rn(o[nd][0], o[nd][1]);
            if (rowB < NTOK)
                *(__half2*)(att + (size_t)(win * NTOK + rowB) * DIM + col) =
                    __floats2half2_rn(o[nd][2], o[nd][3]);
        }
    }
}

// ---------------------------------------------------------------------------
extern "C" void kernel_launch(void* const* d_in, const int* in_sizes, int n_in,
                              void* d_out, int out_size) {
    const float* x     = (const float*)d_in[0];
    const float* Wqkv  = (const float*)d_in[1];
    const float* bqkv  = (const float*)d_in[2];
    const float* Wproj = (const float*)d_in[3];
    const float* bproj = (const float*)d_in[4];
    float* out = (float*)d_out;

    __half *xwh, *qkvh, *atth, *wt, *wtp;
    float *po;
    cudaGetSymbolAddress((void**)&xwh,  g_xwh);
    cudaGetSymbolAddress((void**)&qkvh, g_qkvh);
    cudaGetSymbolAddress((void**)&atth, g_atth);
    cudaGetSymbolAddress((void**)&po,   g_out);
    cudaGetSymbolAddress((void**)&wt,   g_wt);
    cudaGetSymbolAddress((void**)&wtp,  g_wtp);

    const int gemm_smem = 2 * STAGE_B + 1024;
    cudaFuncSetAttribute(hgemm<__half>, cudaFuncAttributeMaxDynamicSharedMemorySize, gemm_smem);
    cudaFuncSetAttribute(hgemm<float>,  cudaFuncAttributeMaxDynamicSharedMemorySize, gemm_smem);
    const int attn_smem = 4 * AW_BYTES;
    cudaFuncSetAttribute(attn_mma, cudaFuncAttributeMaxDynamicSharedMemorySize, attn_smem);

    transpose_w<<<dim3(QKVN / 32, DIM / 32), dim3(32, 8)>>>(Wqkv, wt, DIM, QKVN);
    transpose_w<<<dim3(DIM / 32, DIM / 32), dim3(32, 8)>>>(Wproj, wtp, DIM, DIM);
    gather_win<<<dim3(6, HW, BB), 256>>>(x, xwh);
    hgemm<__half><<<dim3(QKVN / 128, ROWS / 128), 256, gemm_smem>>>(
        xwh, wt, bqkv, qkvh, ROWS, QKVN, DIM);
    attn_mma<<<NWIN * HEADS / 4, 128, attn_smem>>>(qkvh, atth);
    hgemm<float><<<dim3(DIM / 128, ROWS / 128), 256, gemm_smem>>>(
        atth, wtp, bproj, po, ROWS, DIM, DIM);
    scatter_win<<<dim3(6, HW, BB), 256>>>(po, out);
}

// round 7
// speedup vs baseline: 5.0835x; 1.0065x over previous
#include <cuda_runtime.h>
#include <cuda_fp16.h>
#include <math.h>
#include <stdint.h>

#define BB    16
#define DIM   384
#define HW    56
#define WS    7
#define NWIN  (BB * 8 * 8)       // 1024
#define NTOK  49
#define ROWS  (NWIN * NTOK)      // 50176
#define HEADS 12
#define HD    32
#define QKVN  (3 * DIM)          // 1152

// Scratch (device globals — no allocation allowed in kernel_launch)
__device__ __align__(128) __half g_xwh [(size_t)ROWS * DIM];
__device__ __align__(128) __half g_qkvh[(size_t)ROWS * QKVN];
__device__ __align__(128) __half g_atth[(size_t)ROWS * DIM];
__device__ __align__(128) float  g_out [(size_t)ROWS * DIM];
__device__ __align__(128) __half g_wt  [(size_t)QKVN * DIM];
__device__ __align__(128) __half g_wtp [(size_t)DIM * DIM];

// ---------------------------------------------------------------------------
// PTX helpers
// ---------------------------------------------------------------------------
__device__ __forceinline__ uint32_t smem_u32(const void* p) {
    uint32_t a;
    asm("{ .reg .u64 t; cvta.to.shared.u64 t, %1; cvt.u32.u64 %0, t; }"
        : "=r"(a) : "l"(p));
    return a;
}
__device__ __forceinline__ void cp16(uint32_t dst, const void* src) {
    asm volatile("cp.async.cg.shared.global [%0], [%1], 16;"
                 :: "r"(dst), "l"(src));
}
__device__ __forceinline__ void ldsm_x4(uint32_t* r, uint32_t addr) {
    asm volatile("ldmatrix.sync.aligned.m8n8.x4.shared.b16 {%0,%1,%2,%3}, [%4];"
                 : "=r"(r[0]), "=r"(r[1]), "=r"(r[2]), "=r"(r[3]) : "r"(addr));
}
__device__ __forceinline__ void ldsm_x2(uint32_t* r, uint32_t addr) {
    asm volatile("ldmatrix.sync.aligned.m8n8.x2.shared.b16 {%0,%1}, [%2];"
                 : "=r"(r[0]), "=r"(r[1]) : "r"(addr));
}
__device__ __forceinline__ void ldsm_x2t(uint32_t* r, uint32_t addr) {
    asm volatile("ldmatrix.sync.aligned.m8n8.x2.trans.shared.b16 {%0,%1}, [%2];"
                 : "=r"(r[0]), "=r"(r[1]) : "r"(addr));
}
__device__ __forceinline__ void mma16816(float* c, const uint32_t* a, const uint32_t* b) {
    asm volatile(
        "mma.sync.aligned.m16n8k16.row.col.f32.f16.f16.f32 "
        "{%0,%1,%2,%3}, {%4,%5,%6,%7}, {%8,%9}, {%0,%1,%2,%3};"
        : "+f"(c[0]), "+f"(c[1]), "+f"(c[2]), "+f"(c[3])
        : "r"(a[0]), "r"(a[1]), "r"(a[2]), "r"(a[3]), "r"(b[0]), "r"(b[1]));
}
// pack two floats into one uint32 holding a half2 (full 32 bits)
__device__ __forceinline__ uint32_t pack_h2(float a, float b) {
    __half2 h = __floats2half2_rn(a, b);
    return *reinterpret_cast<uint32_t*>(&h);
}

// ---------------------------------------------------------------------------
// Gather: x [B, D, H, W] -> xwh [win*49+t, D] (half)
// ---------------------------------------------------------------------------
__global__ __launch_bounds__(256) void gather_win(const float* __restrict__ x,
                                                  __half* __restrict__ xw) {
    __shared__ float tile[64][57];
    const int dc = blockIdx.x;
    const int hh = blockIdx.y;
    const int b  = blockIdx.z;
    const float* xp = x + (((size_t)b * DIM + dc * 64) * HW + hh) * HW;
    for (int i = threadIdx.x; i < 64 * HW; i += 256) {
        int d = i / HW, w = i % HW;
        tile[d][w] = xp[(size_t)d * HW * HW + w];
    }
    __syncthreads();
    const int wh = hh / WS, r = hh % WS;
    for (int i = threadIdx.x; i < 64 * HW; i += 256) {
        int d = i & 63, w = i >> 6;
        int win = b * 64 + wh * 8 + (w / 7);
        int t   = r * 7 + (w % 7);
        xw[(size_t)(win * NTOK + t) * DIM + dc * 64 + d] = __float2half(tile[d][w]);
    }
}

// ---------------------------------------------------------------------------
// Scatter: pout [win*49+t, D] (f32) -> y [B, D, H, W]
// ---------------------------------------------------------------------------
__global__ __launch_bounds__(256) void scatter_win(const float* __restrict__ pout,
                                                   float* __restrict__ y) {
    __shared__ float tile[64][57];
    const int dc = blockIdx.x;
    const int hh = blockIdx.y;
    const int b  = blockIdx.z;
    const int wh = hh / WS, r = hh % WS;
    for (int i = threadIdx.x; i < 64 * HW; i += 256) {
        int d = i & 63, w = i >> 6;
        int win = b * 64 + wh * 8 + (w / 7);
        int t   = r * 7 + (w % 7);
        tile[d][w] = pout[(size_t)(win * NTOK + t) * DIM + dc * 64 + d];
    }
    __syncthreads();
    float* yp = y + (((size_t)b * DIM + dc * 64) * HW + hh) * HW;
    for (int i = threadIdx.x; i < 64 * HW; i += 256) {
        int d = i / HW, w = i % HW;
        yp[(size_t)d * HW * HW + w] = tile[d][w];
    }
}

// ---------------------------------------------------------------------------
// Weight transpose to half: W [K, N] f32 -> Wt [N, K] half
// ---------------------------------------------------------------------------
__global__ void transpose_w(const float* __restrict__ W, __half* __restrict__ Wt,
                            int K, int N) {
    __shared__ float t[32][33];
    int n0 = blockIdx.x * 32, k0 = blockIdx.y * 32;
    int x = threadIdx.x, y = threadIdx.y;
    for (int i = y; i < 32; i += 8)
        t[i][x] = W[(size_t)(k0 + i) * N + n0 + x];
    __syncthreads();
    for (int i = y; i < 32; i += 8)
        Wt[(size_t)(n0 + i) * K + k0 + x] = __float2half(t[x][i]);
}

// ---------------------------------------------------------------------------
// HGEMM: C[M,N] = A[M,K] @ Bt[N,K]^T + bias[N]; OutT = float or __half
// 128x128 tile, BK=64, SW128 swizzle, THREE-stage cp.async pipeline with
// prefetch distance 2 and ONE __syncthreads per chunk.
// ---------------------------------------------------------------------------
#define STAGE_B 32768

template<typename OutT>
__global__ __launch_bounds__(256, 2) void hgemm(const __half* __restrict__ A,
                                                const __half* __restrict__ Bt,
                                                const float* __restrict__ bias,
                                                OutT* __restrict__ C,
                                                int M, int N, int K) {
    extern __shared__ char dsm[];
    const uint32_t sb = (smem_u32(dsm) + 1023u) & ~1023u;

    const int tid  = threadIdx.x;
    const int wid  = tid >> 5, lane = tid & 31;
    const int wm   = wid & 1;
    const int wn   = wid >> 1;

    const __half* Ap = A  + (size_t)blockIdx.y * 128 * K;
    const __half* Bp = Bt + (size_t)blockIdx.x * 128 * K;
    const int NC = K >> 6;

    auto load_stage = [&](int stage, int k0) {
        const uint32_t sA = sb + stage * STAGE_B, sB = sA + 16384;
#pragma unroll
        for (int i = 0; i < 4; i++) {
            int seg = tid + 256 * i;
            int row = seg >> 3, j = seg & 7;
            uint32_t dst = (uint32_t)(row * 128 + ((j ^ (row & 7)) << 4));
            cp16(sA + dst, Ap + (size_t)row * K + k0 + j * 8);
            cp16(sB + dst, Bp + (size_t)row * K + k0 + j * 8);
        }
        asm volatile("cp.async.commit_group;" ::: "memory");
    };

    // prologue: fill stages 0 and 1
    load_stage(0, 0);
    if (NC > 1) load_stage(1, 64);

    float acc[4][4][4] = {};
    const int arow = wm * 64 + (lane & 15);
    const int ac   = lane >> 4;
    const int brow = wn * 32 + (lane & 7);
    const int bc   = (lane >> 3) & 1;
    const int arx  = arow & 7, brx = brow & 7;

    for (int c = 0; c < NC; c++) {
        // group c must be complete (group c+1 may stay in flight)
        if (c + 1 < NC) asm volatile("cp.async.wait_group 1;" ::: "memory");
        else            asm volatile("cp.async.wait_group 0;" ::: "memory");
        // one barrier: makes stage c visible to all warps AND guarantees every
        // warp finished reading stage (c+2)%3 back in iteration c-1
        __syncthreads();
        if (c + 2 < NC) load_stage((c + 2) % 3, (c + 2) * 64);

        const uint32_t sA = sb + (c % 3) * STAGE_B, sB = sA + 16384;
#pragma unroll
        for (int ks = 0; ks < 4; ks++) {
            uint32_t af[4][4], bf[4][2];
#pragma unroll
            for (int mt = 0; mt < 4; mt++) {
                int row = arow + mt * 16;
                uint32_t addr = sA + (uint32_t)(row * 128 +
                                (((ks * 2 + ac) ^ arx) << 4));
                ldsm_x4(af[mt], addr);
            }
#pragma unroll
            for (int nt = 0; nt < 4; nt++) {
                int row = brow + nt * 8;
                uint32_t addr = sB + (uint32_t)(row * 128 +
                                (((ks * 2 + bc) ^ brx) << 4));
                ldsm_x2(bf[nt], addr);
            }
#pragma unroll
            for (int mt = 0; mt < 4; mt++)
#pragma unroll
                for (int nt = 0; nt < 4; nt++)
                    mma16816(acc[mt][nt], af[mt], bf[nt]);
        }
    }

    const int r0 = blockIdx.y * 128 + wm * 64 + (lane >> 2);
    const int c0 = blockIdx.x * 128 + wn * 32 + (lane & 3) * 2;
#pragma unroll
    for (int mt = 0; mt < 4; mt++) {
#pragma unroll
        for (int nt = 0; nt < 4; nt++) {
            int r = r0 + mt * 16, cc = c0 + nt * 8;
            float b0 = bias[cc], b1 = bias[cc + 1];
            float v00 = acc[mt][nt][0] + b0, v01 = acc[mt][nt][1] + b1;
            float v10 = acc[mt][nt][2] + b0, v11 = acc[mt][nt][3] + b1;
            if constexpr (sizeof(OutT) == 2) {
                *(__half2*)((__half*)C + (size_t)r * N + cc)       = __floats2half2_rn(v00, v01);
                *(__half2*)((__half*)C + (size_t)(r + 8) * N + cc) = __floats2half2_rn(v10, v11);
            } else {
                *(float2*)((float*)C + (size_t)r * N + cc)       = make_float2(v00, v01);
                *(float2*)((float*)C + (size_t)(r + 8) * N + cc) = make_float2(v10, v11);
            }
        }
    }
}

// ---------------------------------------------------------------------------
// Tensor-core attention: one warp per (window, head).
// q/k/v staged to smem: 64 rows x 32 half, row stride 80B (conflict-free).
// S = Q K^T (m16n8k16), masked softmax in registers, O = P V.
// ---------------------------------------------------------------------------
#define AW_BYTES (3 * 64 * 80)   // per-warp smem: q, k, v

__global__ __launch_bounds__(128) void attn_mma(const __half* __restrict__ qkv,
                                                __half* __restrict__ att) {
    extern __shared__ char sm[];
    const int warp = threadIdx.x >> 5, lane = threadIdx.x & 31;
    const int pairid = blockIdx.x * 4 + warp;
    const int win = pairid / HEADS, h = pairid % HEADS;

    char* smp = sm + warp * AW_BYTES;
    const uint32_t base = smem_u32(smp);
    const uint32_t sq = base, sk = base + 5120, sv = base + 10240;

    const __half* qp = qkv + (size_t)win * NTOK * QKVN + h * HD;

    // stage q,k,v (49 rows x 64B each) via cp.async
#pragma unroll
    for (int m = 0; m < 3; m++) {
        const uint32_t dstb = base + m * 5120;
        const __half* src = qp + m * DIM;
        for (int i = lane; i < 196; i += 32) {
            int t = i >> 2, seg = i & 3;
            cp16(dstb + (uint32_t)(t * 80 + seg * 16), src + (size_t)t * QKVN + seg * 8);
        }
    }
    asm volatile("cp.async.commit_group;" ::: "memory");
    // zero pad rows 49..63 of q,k,v
    const float4 z4 = make_float4(0.f, 0.f, 0.f, 0.f);
    for (int i = lane; i < 225; i += 32) {
        int m = i / 75, rem = i % 75;
        int row = 49 + rem / 5, seg = rem % 5;
        *(float4*)(smp + m * 5120 + row * 80 + seg * 16) = z4;
    }
    asm volatile("cp.async.wait_group 0;" ::: "memory");
    __syncwarp();

    const int r   = lane >> 2;
    const int cpr = lane & 3;

    // Hoisted K fragments (B operand of S): kb[nt][ks][2]
    uint32_t kb[7][2][2];
#pragma unroll
    for (int nt = 0; nt < 7; nt++)
#pragma unroll
        for (int ks = 0; ks < 2; ks++) {
            uint32_t addr = sk + (uint32_t)((nt * 8 + (lane & 7)) * 80 +
                            (ks * 2 + ((lane >> 3) & 1)) * 16);
            ldsm_x2(kb[nt][ks], addr);
        }
    // Hoisted V fragments (B operand of O, via trans): vb[ks][nd][2]
    uint32_t vb[4][4][2];
#pragma unroll
    for (int ks = 0; ks < 4; ks++)
#pragma unroll
        for (int nd = 0; nd < 4; nd++) {
            uint32_t addr = sv + (uint32_t)((ks * 16 + (lane & 15)) * 80 + nd * 16);
            ldsm_x2t(vb[ks][nd], addr);
        }

    const float CSC = 0.25506153f;  // (1/sqrt(32)) * log2(e)

#pragma unroll
    for (int mt = 0; mt < 4; mt++) {
        uint32_t qa[2][4];
#pragma unroll
        for (int ks = 0; ks < 2; ks++) {
            uint32_t addr = sq + (uint32_t)((mt * 16 + (lane & 15)) * 80 +
                            (ks * 2 + (lane >> 4)) * 16);
            ldsm_x4(qa[ks], addr);
        }
        float s[7][4] = {};
#pragma unroll
        for (int nt = 0; nt < 7; nt++) {
            mma16816(s[nt], qa[0], kb[nt][0]);
            mma16816(s[nt], qa[1], kb[nt][1]);
        }
        // scale (log2-domain) + mask cols >= 49 (tile nt=6 holds cols 48..55)
#pragma unroll
        for (int nt = 0; nt < 7; nt++)
#pragma unroll
            for (int j = 0; j < 4; j++) s[nt][j] *= CSC;
        if (cpr != 0) { s[6][0] = s[6][1] = s[6][2] = s[6][3] = -1e30f; }
        else          { s[6][1] = s[6][3] = -1e30f; }

        // rowwise max over the 4-lane group
        float mA = -1e30f, mB = -1e30f;
#pragma unroll
        for (int nt = 0; nt < 7; nt++) {
            mA = fmaxf(mA, fmaxf(s[nt][0], s[nt][1]));
            mB = fmaxf(mB, fmaxf(s[nt][2], s[nt][3]));
        }
        mA = fmaxf(mA, __shfl_xor_sync(0xffffffffu, mA, 1));
        mA = fmaxf(mA, __shfl_xor_sync(0xffffffffu, mA, 2));
        mB = fmaxf(mB, __shfl_xor_sync(0xffffffffu, mB, 1));
        mB = fmaxf(mB, __shfl_xor_sync(0xffffffffu, mB, 2));

        float sumA = 0.f, sumB = 0.f;
#pragma unroll
        for (int nt = 0; nt < 7; nt++) {
            s[nt][0] = exp2f(s[nt][0] - mA);
            s[nt][1] = exp2f(s[nt][1] - mA);
            s[nt][2] = exp2f(s[nt][2] - mB);
            s[nt][3] = exp2f(s[nt][3] - mB);
            sumA += s[nt][0] + s[nt][1];
            sumB += s[nt][2] + s[nt][3];
        }
        sumA += __shfl_xor_sync(0xffffffffu, sumA, 1);
        sumA += __shfl_xor_sync(0xffffffffu, sumA, 2);
        sumB += __shfl_xor_sync(0xffffffffu, sumB, 1);
        sumB += __shfl_xor_sync(0xffffffffu, sumB, 2);
        const float invA = 1.0f / sumA, invB = 1.0f / sumB;

        // convert P to A-operand fragments: pa[ks][4]
        uint32_t pa[4][4];
#pragma unroll
        for (int ks = 0; ks < 4; ks++) {
            int nt0 = 2 * ks, nt1 = 2 * ks + 1;
            pa[ks][0] = pack_h2(s[nt0][0] * invA, s[nt0][1] * invA);
            pa[ks][1] = pack_h2(s[nt0][2] * invB, s[nt0][3] * invB);
            if (nt1 < 7) {
                pa[ks][2] = pack_h2(s[nt1][0] * invA, s[nt1][1] * invA);
                pa[ks][3] = pack_h2(s[nt1][2] * invB, s[nt1][3] * invB);
            } else {
                pa[ks][2] = 0u; pa[ks][3] = 0u;
            }
        }

        float o[4][4] = {};
#pragma unroll
        for (int ks = 0; ks < 4; ks++)
#pragma unroll
            for (int nd = 0; nd < 4; nd++)
                mma16816(o[nd], pa[ks], vb[ks][nd]);

        // store O rows (mt*16 + r) and (+8), cols nd*8 + cpr*2
        const int rowA = mt * 16 + r;
        const int rowB = rowA + 8;
#pragma unroll
        for (int nd = 0; nd < 4; nd++) {
            int col = h * HD + nd * 8 + cpr * 2;
            if (rowA < NTOK)
                *(__half2*)(att + (size_t)(win * NTOK + rowA) * DIM + col) =
                    __floats2half2_rn(o[nd][0], o[nd][1]);
            if (rowB < NTOK)
                *(__half2*)(att + (size_t)(win * NTOK + rowB) * DIM + col) =
                    __floats2half2_rn(o[nd][2], o[nd][3]);
        }
    }
}

// ---------------------------------------------------------------------------
extern "C" void kernel_launch(void* const* d_in, const int* in_sizes, int n_in,
                              void* d_out, int out_size) {
    const float* x     = (const float*)d_in[0];
    const float* Wqkv  = (const float*)d_in[1];
    const float* bqkv  = (const float*)d_in[2];
    const float* Wproj = (const float*)d_in[3];
    const float* bproj = (const float*)d_in[4];
    float* out = (float*)d_out;

    __half *xwh, *qkvh, *atth, *wt, *wtp;
    float *po;
    cudaGetSymbolAddress((void**)&xwh,  g_xwh);
    cudaGetSymbolAddress((void**)&qkvh, g_qkvh);
    cudaGetSymbolAddress((void**)&atth, g_atth);
    cudaGetSymbolAddress((void**)&po,   g_out);
    cudaGetSymbolAddress((void**)&wt,   g_wt);
    cudaGetSymbolAddress((void**)&wtp,  g_wtp);

    const int gemm_smem = 3 * STAGE_B + 1024;   // 3-stage pipeline
    cudaFuncSetAttribute(hgemm<__half>, cudaFuncAttributeMaxDynamicSharedMemorySize, gemm_smem);
    cudaFuncSetAttribute(hgemm<float>,  cudaFuncAttributeMaxDynamicSharedMemorySize, gemm_smem);
    const int attn_smem = 4 * AW_BYTES;
    cudaFuncSetAttribute(attn_mma, cudaFuncAttributeMaxDynamicSharedMemorySize, attn_smem);

    transpose_w<<<dim3(QKVN / 32, DIM / 32), dim3(32, 8)>>>(Wqkv, wt, DIM, QKVN);
    transpose_w<<<dim3(DIM / 32, DIM / 32), dim3(32, 8)>>>(Wproj, wtp, DIM, DIM);
    gather_win<<<dim3(6, HW, BB), 256>>>(x, xwh);
    hgemm<__half><<<dim3(QKVN / 128, ROWS / 128), 256, gemm_smem>>>(
        xwh, wt, bqkv, qkvh, ROWS, QKVN, DIM);
    attn_mma<<<NWIN * HEADS / 4, 128, attn_smem>>>(qkvh, atth);
    hgemm<float><<<dim3(DIM / 128, ROWS / 128), 256, gemm_smem>>>(
        atth, wtp, bproj, po, ROWS, DIM, DIM);
    scatter_win<<<dim3(6, HW, BB), 256>>>(po, out);
}

// round 8
// speedup vs baseline: 5.2583x; 1.0344x over previous
#include <cuda_runtime.h>
#include <cuda_fp16.h>
#include <math.h>
#include <stdint.h>

#define BB    16
#define DIM   384
#define HW    56
#define WS    7
#define NWIN  (BB * 8 * 8)       // 1024
#define NTOK  49
#define ROWS  (NWIN * NTOK)      // 50176
#define HEADS 12
#define HD    32
#define QKVN  (3 * DIM)          // 1152

// Scratch (device globals — no allocation allowed in kernel_launch)
__device__ __align__(128) __half g_xwh [(size_t)ROWS * DIM];
__device__ __align__(128) __half g_qkvh[(size_t)ROWS * QKVN];
__device__ __align__(128) __half g_atth[(size_t)ROWS * DIM];
__device__ __align__(128) float  g_out [(size_t)ROWS * DIM];
__device__ __align__(128) __half g_wt  [(size_t)QKVN * DIM];
__device__ __align__(128) __half g_wtp [(size_t)DIM * DIM];

// ---------------------------------------------------------------------------
// PTX helpers
// ---------------------------------------------------------------------------
__device__ __forceinline__ uint32_t smem_u32(const void* p) {
    uint32_t a;
    asm("{ .reg .u64 t; cvta.to.shared.u64 t, %1; cvt.u32.u64 %0, t; }"
        : "=r"(a) : "l"(p));
    return a;
}
__device__ __forceinline__ void cp16(uint32_t dst, const void* src) {
    asm volatile("cp.async.cg.shared.global [%0], [%1], 16;"
                 :: "r"(dst), "l"(src));
}
__device__ __forceinline__ void ldsm_x4(uint32_t* r, uint32_t addr) {
    asm volatile("ldmatrix.sync.aligned.m8n8.x4.shared.b16 {%0,%1,%2,%3}, [%4];"
                 : "=r"(r[0]), "=r"(r[1]), "=r"(r[2]), "=r"(r[3]) : "r"(addr));
}
__device__ __forceinline__ void ldsm_x2(uint32_t* r, uint32_t addr) {
    asm volatile("ldmatrix.sync.aligned.m8n8.x2.shared.b16 {%0,%1}, [%2];"
                 : "=r"(r[0]), "=r"(r[1]) : "r"(addr));
}
__device__ __forceinline__ void ldsm_x2t(uint32_t* r, uint32_t addr) {
    asm volatile("ldmatrix.sync.aligned.m8n8.x2.trans.shared.b16 {%0,%1}, [%2];"
                 : "=r"(r[0]), "=r"(r[1]) : "r"(addr));
}
__device__ __forceinline__ void mma16816(float* c, const uint32_t* a, const uint32_t* b) {
    asm volatile(
        "mma.sync.aligned.m16n8k16.row.col.f32.f16.f16.f32 "
        "{%0,%1,%2,%3}, {%4,%5,%6,%7}, {%8,%9}, {%0,%1,%2,%3};"
        : "+f"(c[0]), "+f"(c[1]), "+f"(c[2]), "+f"(c[3])
        : "r"(a[0]), "r"(a[1]), "r"(a[2]), "r"(a[3]), "r"(b[0]), "r"(b[1]));
}
// pack two floats into one uint32 holding a half2 (full 32 bits)
__device__ __forceinline__ uint32_t pack_h2(float a, float b) {
    __half2 h = __floats2half2_rn(a, b);
    return *reinterpret_cast<uint32_t*>(&h);
}

// ---------------------------------------------------------------------------
// Gather: x [B, D, H, W] -> xwh [win*49+t, D] (half)
// ---------------------------------------------------------------------------
__global__ __launch_bounds__(256) void gather_win(const float* __restrict__ x,
                                                  __half* __restrict__ xw) {
    __shared__ float tile[64][57];
    const int dc = blockIdx.x;
    const int hh = blockIdx.y;
    const int b  = blockIdx.z;
    const float* xp = x + (((size_t)b * DIM + dc * 64) * HW + hh) * HW;
    for (int i = threadIdx.x; i < 64 * HW; i += 256) {
        int d = i / HW, w = i % HW;
        tile[d][w] = xp[(size_t)d * HW * HW + w];
    }
    __syncthreads();
    const int wh = hh / WS, r = hh % WS;
    for (int i = threadIdx.x; i < 64 * HW; i += 256) {
        int d = i & 63, w = i >> 6;
        int win = b * 64 + wh * 8 + (w / 7);
        int t   = r * 7 + (w % 7);
        xw[(size_t)(win * NTOK + t) * DIM + dc * 64 + d] = __float2half(tile[d][w]);
    }
}

// ---------------------------------------------------------------------------
// Scatter: pout [win*49+t, D] (f32) -> y [B, D, H, W]
// ---------------------------------------------------------------------------
__global__ __launch_bounds__(256) void scatter_win(const float* __restrict__ pout,
                                                   float* __restrict__ y) {
    __shared__ float tile[64][57];
    const int dc = blockIdx.x;
    const int hh = blockIdx.y;
    const int b  = blockIdx.z;
    const int wh = hh / WS, r = hh % WS;
    for (int i = threadIdx.x; i < 64 * HW; i += 256) {
        int d = i & 63, w = i >> 6;
        int win = b * 64 + wh * 8 + (w / 7);
        int t   = r * 7 + (w % 7);
        tile[d][w] = pout[(size_t)(win * NTOK + t) * DIM + dc * 64 + d];
    }
    __syncthreads();
    float* yp = y + (((size_t)b * DIM + dc * 64) * HW + hh) * HW;
    for (int i = threadIdx.x; i < 64 * HW; i += 256) {
        int d = i / HW, w = i % HW;
        yp[(size_t)d * HW * HW + w] = tile[d][w];
    }
}

// ---------------------------------------------------------------------------
// Weight transpose to half: W [K, N] f32 -> Wt [N, K] half
// ---------------------------------------------------------------------------
__global__ void transpose_w(const float* __restrict__ W, __half* __restrict__ Wt,
                            int K, int N) {
    __shared__ float t[32][33];
    int n0 = blockIdx.x * 32, k0 = blockIdx.y * 32;
    int x = threadIdx.x, y = threadIdx.y;
    for (int i = y; i < 32; i += 8)
        t[i][x] = W[(size_t)(k0 + i) * N + n0 + x];
    __syncthreads();
    for (int i = y; i < 32; i += 8)
        Wt[(size_t)(n0 + i) * K + k0 + x] = __float2half(t[x][i]);
}

// ---------------------------------------------------------------------------
// HGEMM: C[M,N] = A[M,K] @ Bt[N,K]^T + bias[N]; OutT = float or __half.
// 128x128 tile, BK=64, SW128 swizzle, 3-stage cp.async pipeline.
// K compile-time: NC fully unrolled. B fragments loaded with ldsm_x4 pairs
// (2 n8-tiles per instruction) -> 24 LDSM/chunk instead of 32.
// ---------------------------------------------------------------------------
#define STAGE_B 32768

template<typename OutT, int K>
__global__ __launch_bounds__(256, 2) void hgemm(const __half* __restrict__ A,
                                                const __half* __restrict__ Bt,
                                                const float* __restrict__ bias,
                                                OutT* __restrict__ C,
                                                int M, int N) {
    extern __shared__ char dsm[];
    const uint32_t sb = (smem_u32(dsm) + 1023u) & ~1023u;

    const int tid  = threadIdx.x;
    const int wid  = tid >> 5, lane = tid & 31;
    const int wm   = wid & 1;
    const int wn   = wid >> 1;

    const __half* Ap = A  + (size_t)blockIdx.y * 128 * K;
    const __half* Bp = Bt + (size_t)blockIdx.x * 128 * K;
    constexpr int NC = K >> 6;

    auto load_stage = [&](int stage, int k0) {
        const uint32_t sA = sb + stage * STAGE_B, sB = sA + 16384;
#pragma unroll
        for (int i = 0; i < 4; i++) {
            int seg = tid + 256 * i;
            int row = seg >> 3, j = seg & 7;
            uint32_t dst = (uint32_t)(row * 128 + ((j ^ (row & 7)) << 4));
            cp16(sA + dst, Ap + (size_t)row * K + k0 + j * 8);
            cp16(sB + dst, Bp + (size_t)row * K + k0 + j * 8);
        }
        asm volatile("cp.async.commit_group;" ::: "memory");
    };

    // prologue: fill stages 0 and 1
    load_stage(0, 0);
    if (NC > 1) load_stage(1, 64);

    float acc[4][4][4] = {};
    // A ldmatrix addressing
    const int arow = wm * 64 + (lane & 15);
    const int ac   = lane >> 4;
    const int arx  = arow & 7;
    // B ldmatrix x4 addressing: lanes 0-15 -> nt=2p, lanes 16-31 -> nt=2p+1,
    // within each 16-lane half: lanes&8 selects the k16-half chunk
    const int brow4 = wn * 32 + ((lane >> 4) << 3) + (lane & 7);
    const int bc4   = (lane >> 3) & 1;
    const int brx4  = brow4 & 7;

#pragma unroll
    for (int c = 0; c < NC; c++) {
        if (c + 1 < NC) asm volatile("cp.async.wait_group 1;" ::: "memory");
        else            asm volatile("cp.async.wait_group 0;" ::: "memory");
        __syncthreads();
        if (c + 2 < NC) load_stage((c + 2) % 3, (c + 2) * 64);

        const uint32_t sA = sb + (c % 3) * STAGE_B, sB = sA + 16384;
#pragma unroll
        for (int ks = 0; ks < 4; ks++) {
            uint32_t af[4][4], bf[4][2];
#pragma unroll
            for (int mt = 0; mt < 4; mt++) {
                int row = arow + mt * 16;
                uint32_t addr = sA + (uint32_t)(row * 128 +
                                (((ks * 2 + ac) ^ arx) << 4));
                ldsm_x4(af[mt], addr);
            }
#pragma unroll
            for (int p = 0; p < 2; p++) {   // each x4 fills bf[2p] and bf[2p+1]
                int row = brow4 + p * 16;
                uint32_t addr = sB + (uint32_t)(row * 128 +
                                (((ks * 2 + bc4) ^ (brx4)) << 4));
                uint32_t r4[4];
                ldsm_x4(r4, addr);
                bf[2 * p][0] = r4[0]; bf[2 * p][1] = r4[1];
                bf[2 * p + 1][0] = r4[2]; bf[2 * p + 1][1] = r4[3];
            }
#pragma unroll
            for (int mt = 0; mt < 4; mt++)
#pragma unroll
                for (int nt = 0; nt < 4; nt++)
                    mma16816(acc[mt][nt], af[mt], bf[nt]);
        }
    }

    const int r0 = blockIdx.y * 128 + wm * 64 + (lane >> 2);
    const int c0 = blockIdx.x * 128 + wn * 32 + (lane & 3) * 2;
#pragma unroll
    for (int mt = 0; mt < 4; mt++) {
#pragma unroll
        for (int nt = 0; nt < 4; nt++) {
            int r = r0 + mt * 16, cc = c0 + nt * 8;
            float b0 = bias[cc], b1 = bias[cc + 1];
            float v00 = acc[mt][nt][0] + b0, v01 = acc[mt][nt][1] + b1;
            float v10 = acc[mt][nt][2] + b0, v11 = acc[mt][nt][3] + b1;
            if constexpr (sizeof(OutT) == 2) {
                *(__half2*)((__half*)C + (size_t)r * N + cc)       = __floats2half2_rn(v00, v01);
                *(__half2*)((__half*)C + (size_t)(r + 8) * N + cc) = __floats2half2_rn(v10, v11);
            } else {
                *(float2*)((float*)C + (size_t)r * N + cc)       = make_float2(v00, v01);
                *(float2*)((float*)C + (size_t)(r + 8) * N + cc) = make_float2(v10, v11);
            }
        }
    }
}

// ---------------------------------------------------------------------------
// Tensor-core attention: one warp per (window, head).
// q/k/v staged to smem: 64 rows x 32 half, row stride 80B (conflict-free).
// S = Q K^T (m16n8k16), masked softmax in registers, O = P V.
// ---------------------------------------------------------------------------
#define AW_BYTES (3 * 64 * 80)   // per-warp smem: q, k, v

__global__ __launch_bounds__(128) void attn_mma(const __half* __restrict__ qkv,
                                                __half* __restrict__ att) {
    extern __shared__ char sm[];
    const int warp = threadIdx.x >> 5, lane = threadIdx.x & 31;
    const int pairid = blockIdx.x * 4 + warp;
    const int win = pairid / HEADS, h = pairid % HEADS;

    char* smp = sm + warp * AW_BYTES;
    const uint32_t base = smem_u32(smp);
    const uint32_t sq = base, sk = base + 5120, sv = base + 10240;

    const __half* qp = qkv + (size_t)win * NTOK * QKVN + h * HD;

    // stage q,k,v (49 rows x 64B each) via cp.async
#pragma unroll
    for (int m = 0; m < 3; m++) {
        const uint32_t dstb = base + m * 5120;
        const __half* src = qp + m * DIM;
        for (int i = lane; i < 196; i += 32) {
            int t = i >> 2, seg = i & 3;
            cp16(dstb + (uint32_t)(t * 80 + seg * 16), src + (size_t)t * QKVN + seg * 8);
        }
    }
    asm volatile("cp.async.commit_group;" ::: "memory");
    // zero pad rows 49..63 of q,k,v
    const float4 z4 = make_float4(0.f, 0.f, 0.f, 0.f);
    for (int i = lane; i < 225; i += 32) {
        int m = i / 75, rem = i % 75;
        int row = 49 + rem / 5, seg = rem % 5;
        *(float4*)(smp + m * 5120 + row * 80 + seg * 16) = z4;
    }
    asm volatile("cp.async.wait_group 0;" ::: "memory");
    __syncwarp();

    const int r   = lane >> 2;
    const int cpr = lane & 3;

    // Hoisted K fragments (B operand of S): kb[nt][ks][2]
    uint32_t kb[7][2][2];
#pragma unroll
    for (int nt = 0; nt < 7; nt++)
#pragma unroll
        for (int ks = 0; ks < 2; ks++) {
            uint32_t addr = sk + (uint32_t)((nt * 8 + (lane & 7)) * 80 +
                            (ks * 2 + ((lane >> 3) & 1)) * 16);
            ldsm_x2(kb[nt][ks], addr);
        }
    // Hoisted V fragments (B operand of O, via trans): vb[ks][nd][2]
    uint32_t vb[4][4][2];
#pragma unroll
    for (int ks = 0; ks < 4; ks++)
#pragma unroll
        for (int nd = 0; nd < 4; nd++) {
            uint32_t addr = sv + (uint32_t)((ks * 16 + (lane & 15)) * 80 + nd * 16);
            ldsm_x2t(vb[ks][nd], addr);
        }

    const float CSC = 0.25506153f;  // (1/sqrt(32)) * log2(e)

#pragma unroll
    for (int mt = 0; mt < 4; mt++) {
        uint32_t qa[2][4];
#pragma unroll
        for (int ks = 0; ks < 2; ks++) {
            uint32_t addr = sq + (uint32_t)((mt * 16 + (lane & 15)) * 80 +
                            (ks * 2 + (lane >> 4)) * 16);
            ldsm_x4(qa[ks], addr);
        }
        float s[7][4] = {};
#pragma unroll
        for (int nt = 0; nt < 7; nt++) {
            mma16816(s[nt], qa[0], kb[nt][0]);
            mma16816(s[nt], qa[1], kb[nt][1]);
        }
        // scale (log2-domain) + mask cols >= 49 (tile nt=6 holds cols 48..55)
#pragma unroll
        for (int nt = 0; nt < 7; nt++)
#pragma unroll
            for (int j = 0; j < 4; j++) s[nt][j] *= CSC;
        if (cpr != 0) { s[6][0] = s[6][1] = s[6][2] = s[6][3] = -1e30f; }
        else          { s[6][1] = s[6][3] = -1e30f; }

        // rowwise max over the 4-lane group
        float mA = -1e30f, mB = -1e30f;
#pragma unroll
        for (int nt = 0; nt < 7; nt++) {
            mA = fmaxf(mA, fmaxf(s[nt][0], s[nt][1]));
            mB = fmaxf(mB, fmaxf(s[nt][2], s[nt][3]));
        }
        mA = fmaxf(mA, __shfl_xor_sync(0xffffffffu, mA, 1));
        mA = fmaxf(mA, __shfl_xor_sync(0xffffffffu, mA, 2));
        mB = fmaxf(mB, __shfl_xor_sync(0xffffffffu, mB, 1));
        mB = fmaxf(mB, __shfl_xor_sync(0xffffffffu, mB, 2));

        float sumA = 0.f, sumB = 0.f;
#pragma unroll
        for (int nt = 0; nt < 7; nt++) {
            s[nt][0] = exp2f(s[nt][0] - mA);
            s[nt][1] = exp2f(s[nt][1] - mA);
            s[nt][2] = exp2f(s[nt][2] - mB);
            s[nt][3] = exp2f(s[nt][3] - mB);
            sumA += s[nt][0] + s[nt][1];
            sumB += s[nt][2] + s[nt][3];
        }
        sumA += __shfl_xor_sync(0xffffffffu, sumA, 1);
        sumA += __shfl_xor_sync(0xffffffffu, sumA, 2);
        sumB += __shfl_xor_sync(0xffffffffu, sumB, 1);
        sumB += __shfl_xor_sync(0xffffffffu, sumB, 2);
        const float invA = 1.0f / sumA, invB = 1.0f / sumB;

        // convert P to A-operand fragments: pa[ks][4]
        uint32_t pa[4][4];
#pragma unroll
        for (int ks = 0; ks < 4; ks++) {
            int nt0 = 2 * ks, nt1 = 2 * ks + 1;
            pa[ks][0] = pack_h2(s[nt0][0] * invA, s[nt0][1] * invA);
            pa[ks][1] = pack_h2(s[nt0][2] * invB, s[nt0][3] * invB);
            if (nt1 < 7) {
                pa[ks][2] = pack_h2(s[nt1][0] * invA, s[nt1][1] * invA);
                pa[ks][3] = pack_h2(s[nt1][2] * invB, s[nt1][3] * invB);
            } else {
                pa[ks][2] = 0u; pa[ks][3] = 0u;
            }
        }

        float o[4][4] = {};
#pragma unroll
        for (int ks = 0; ks < 4; ks++)
#pragma unroll
            for (int nd = 0; nd < 4; nd++)
                mma16816(o[nd], pa[ks], vb[ks][nd]);

        // store O rows (mt*16 + r) and (+8), cols nd*8 + cpr*2
        const int rowA = mt * 16 + r;
        const int rowB = rowA + 8;
#pragma unroll
        for (int nd = 0; nd < 4; nd++) {
            int col = h * HD + nd * 8 + cpr * 2;
            if (rowA < NTOK)
                *(__half2*)(att + (size_t)(win * NTOK + rowA) * DIM + col) =
                    __floats2half2_rn(o[nd][0], o[nd][1]);
            if (rowB < NTOK)
                *(__half2*)(att + (size_t)(win * NTOK + rowB) * DIM + col) =
                    __floats2half2_rn(o[nd][2], o[nd][3]);
        }
    }
}

// ---------------------------------------------------------------------------
extern "C" void kernel_launch(void* const* d_in, const int* in_sizes, int n_in,
                              void* d_out, int out_size) {
    const float* x     = (const float*)d_in[0];
    const float* Wqkv  = (const float*)d_in[1];
    const float* bqkv  = (const float*)d_in[2];
    const float* Wproj = (const float*)d_in[3];
    const float* bproj = (const float*)d_in[4];
    float* out = (float*)d_out;

    __half *xwh, *qkvh, *atth, *wt, *wtp;
    float *po;
    cudaGetSymbolAddress((void**)&xwh,  g_xwh);
    cudaGetSymbolAddress((void**)&qkvh, g_qkvh);
    cudaGetSymbolAddress((void**)&atth, g_atth);
    cudaGetSymbolAddress((void**)&po,   g_out);
    cudaGetSymbolAddress((void**)&wt,   g_wt);
    cudaGetSymbolAddress((void**)&wtp,  g_wtp);

    const int gemm_smem = 3 * STAGE_B + 1024;   // 3-stage pipeline
    cudaFuncSetAttribute((const void*)hgemm<__half, DIM>,
                         cudaFuncAttributeMaxDynamicSharedMemorySize, gemm_smem);
    cudaFuncSetAttribute((const void*)hgemm<float, DIM>,
                         cudaFuncAttributeMaxDynamicSharedMemorySize, gemm_smem);
    const int attn_smem = 4 * AW_BYTES;
    cudaFuncSetAttribute(attn_mma, cudaFuncAttributeMaxDynamicSharedMemorySize, attn_smem);

    transpose_w<<<dim3(QKVN / 32, DIM / 32), dim3(32, 8)>>>(Wqkv, wt, DIM, QKVN);
    transpose_w<<<dim3(DIM / 32, DIM / 32), dim3(32, 8)>>>(Wproj, wtp, DIM, DIM);
    gather_win<<<dim3(6, HW, BB), 256>>>(x, xwh);
    hgemm<__half, DIM><<<dim3(QKVN / 128, ROWS / 128), 256, gemm_smem>>>(
        xwh, wt, bqkv, qkvh, ROWS, QKVN);
    attn_mma<<<NWIN * HEADS / 4, 128, attn_smem>>>(qkvh, atth);
    hgemm<float, DIM><<<dim3(DIM / 128, ROWS / 128), 256, gemm_smem>>>(
        atth, wtp, bproj, po, ROWS, DIM);
    scatter_win<<<dim3(6, HW, BB), 256>>>(po, out);
}

// round 9
// speedup vs baseline: 5.3398x; 1.0155x over previous
#include <cuda_runtime.h>
#include <cuda_fp16.h>
#include <math.h>
#include <stdint.h>

#define BB    16
#define DIM   384
#define HW    56
#define WS    7
#define NWIN  (BB * 8 * 8)       // 1024
#define NTOK  49
#define ROWS  (NWIN * NTOK)      // 50176
#define HEADS 12
#define HD    32
#define QKVN  (3 * DIM)          // 1152

// Scratch (device globals — no allocation allowed in kernel_launch)
__device__ __align__(128) __half g_xwh [(size_t)ROWS * DIM];
__device__ __align__(128) __half g_qkvh[(size_t)ROWS * QKVN];
__device__ __align__(128) __half g_atth[(size_t)ROWS * DIM];
__device__ __align__(128) float  g_out [(size_t)ROWS * DIM];
__device__ __align__(128) __half g_wt  [(size_t)QKVN * DIM];
__device__ __align__(128) __half g_wtp [(size_t)DIM * DIM];

// ---------------------------------------------------------------------------
// PTX helpers
// ---------------------------------------------------------------------------
__device__ __forceinline__ uint32_t smem_u32(const void* p) {
    uint32_t a;
    asm("{ .reg .u64 t; cvta.to.shared.u64 t, %1; cvt.u32.u64 %0, t; }"
        : "=r"(a) : "l"(p));
    return a;
}
__device__ __forceinline__ void cp16(uint32_t dst, const void* src) {
    asm volatile("cp.async.cg.shared.global [%0], [%1], 16;"
                 :: "r"(dst), "l"(src));
}
__device__ __forceinline__ void ldsm_x4(uint32_t* r, uint32_t addr) {
    asm volatile("ldmatrix.sync.aligned.m8n8.x4.shared.b16 {%0,%1,%2,%3}, [%4];"
                 : "=r"(r[0]), "=r"(r[1]), "=r"(r[2]), "=r"(r[3]) : "r"(addr));
}
__device__ __forceinline__ void ldsm_x2(uint32_t* r, uint32_t addr) {
    asm volatile("ldmatrix.sync.aligned.m8n8.x2.shared.b16 {%0,%1}, [%2];"
                 : "=r"(r[0]), "=r"(r[1]) : "r"(addr));
}
__device__ __forceinline__ void ldsm_x2t(uint32_t* r, uint32_t addr) {
    asm volatile("ldmatrix.sync.aligned.m8n8.x2.trans.shared.b16 {%0,%1}, [%2];"
                 : "=r"(r[0]), "=r"(r[1]) : "r"(addr));
}
__device__ __forceinline__ void mma16816(float* c, const uint32_t* a, const uint32_t* b) {
    asm volatile(
        "mma.sync.aligned.m16n8k16.row.col.f32.f16.f16.f32 "
        "{%0,%1,%2,%3}, {%4,%5,%6,%7}, {%8,%9}, {%0,%1,%2,%3};"
        : "+f"(c[0]), "+f"(c[1]), "+f"(c[2]), "+f"(c[3])
        : "r"(a[0]), "r"(a[1]), "r"(a[2]), "r"(a[3]), "r"(b[0]), "r"(b[1]));
}
// pack two floats into one uint32 holding a half2 (full 32 bits)
__device__ __forceinline__ uint32_t pack_h2(float a, float b) {
    __half2 h = __floats2half2_rn(a, b);
    return *reinterpret_cast<uint32_t*>(&h);
}
// single-instruction MUFU exp2 (exp2f without fast-math is a multi-instr seq)
__device__ __forceinline__ float ex2(float x) {
    float y;
    asm("ex2.approx.f32 %0, %1;" : "=f"(y) : "f"(x));
    return y;
}

// ---------------------------------------------------------------------------
// Gather: x [B, D, H, W] -> xwh [win*49+t, D] (half)
// ---------------------------------------------------------------------------
__global__ __launch_bounds__(256) void gather_win(const float* __restrict__ x,
                                                  __half* __restrict__ xw) {
    __shared__ float tile[64][57];
    const int dc = blockIdx.x;
    const int hh = blockIdx.y;
    const int b  = blockIdx.z;
    const float* xp = x + (((size_t)b * DIM + dc * 64) * HW + hh) * HW;
    for (int i = threadIdx.x; i < 64 * HW; i += 256) {
        int d = i / HW, w = i % HW;
        tile[d][w] = xp[(size_t)d * HW * HW + w];
    }
    __syncthreads();
    const int wh = hh / WS, r = hh % WS;
    for (int i = threadIdx.x; i < 64 * HW; i += 256) {
        int d = i & 63, w = i >> 6;
        int win = b * 64 + wh * 8 + (w / 7);
        int t   = r * 7 + (w % 7);
        xw[(size_t)(win * NTOK + t) * DIM + dc * 64 + d] = __float2half(tile[d][w]);
    }
}

// ---------------------------------------------------------------------------
// Scatter: pout [win*49+t, D] (f32) -> y [B, D, H, W]
// ---------------------------------------------------------------------------
__global__ __launch_bounds__(256) void scatter_win(const float* __restrict__ pout,
                                                   float* __restrict__ y) {
    __shared__ float tile[64][57];
    const int dc = blockIdx.x;
    const int hh = blockIdx.y;
    const int b  = blockIdx.z;
    const int wh = hh / WS, r = hh % WS;
    for (int i = threadIdx.x; i < 64 * HW; i += 256) {
        int d = i & 63, w = i >> 6;
        int win = b * 64 + wh * 8 + (w / 7);
        int t   = r * 7 + (w % 7);
        tile[d][w] = pout[(size_t)(win * NTOK + t) * DIM + dc * 64 + d];
    }
    __syncthreads();
    float* yp = y + (((size_t)b * DIM + dc * 64) * HW + hh) * HW;
    for (int i = threadIdx.x; i < 64 * HW; i += 256) {
        int d = i / HW, w = i % HW;
        yp[(size_t)d * HW * HW + w] = tile[d][w];
    }
}

// ---------------------------------------------------------------------------
// Weight transpose to half: W [K, N] f32 -> Wt [N, K] half
// ---------------------------------------------------------------------------
__global__ void transpose_w(const float* __restrict__ W, __half* __restrict__ Wt,
                            int K, int N) {
    __shared__ float t[32][33];
    int n0 = blockIdx.x * 32, k0 = blockIdx.y * 32;
    int x = threadIdx.x, y = threadIdx.y;
    for (int i = y; i < 32; i += 8)
        t[i][x] = W[(size_t)(k0 + i) * N + n0 + x];
    __syncthreads();
    for (int i = y; i < 32; i += 8)
        Wt[(size_t)(n0 + i) * K + k0 + x] = __float2half(t[x][i]);
}

// ---------------------------------------------------------------------------
// HGEMM: C[M,N] = A[M,K] @ Bt[N,K]^T + bias[N]; OutT = float or __half.
// 128x128 CTA tile, FOUR warps in a 2x2 grid, 64x64 per warp.
// BK=64, SW128 swizzle, 3-stage cp.async pipeline, K compile-time.
// MMA:LDSM per k16-step = 32:8 (vs 16:6 before).
// ---------------------------------------------------------------------------
#define STAGE_B 32768

template<typename OutT, int K>
__global__ __launch_bounds__(128, 2) void hgemm(const __half* __restrict__ A,
                                                const __half* __restrict__ Bt,
                                                const float* __restrict__ bias,
                                                OutT* __restrict__ C,
                                                int M, int N) {
    extern __shared__ char dsm[];
    const uint32_t sb = (smem_u32(dsm) + 1023u) & ~1023u;

    const int tid  = threadIdx.x;
    const int wid  = tid >> 5, lane = tid & 31;
    const int wm   = wid & 1;        // 0..1 -> 64-row block
    const int wn   = wid >> 1;       // 0..1 -> 64-col block

    const __half* Ap = A  + (size_t)blockIdx.y * 128 * K;
    const __half* Bp = Bt + (size_t)blockIdx.x * 128 * K;
    constexpr int NC = K >> 6;

    auto load_stage = [&](int stage, int k0) {
        const uint32_t sA = sb + stage * STAGE_B, sB = sA + 16384;
#pragma unroll
        for (int i = 0; i < 8; i++) {
            int seg = tid + 128 * i;
            int row = seg >> 3, j = seg & 7;
            uint32_t dst = (uint32_t)(row * 128 + ((j ^ (row & 7)) << 4));
            cp16(sA + dst, Ap + (size_t)row * K + k0 + j * 8);
            cp16(sB + dst, Bp + (size_t)row * K + k0 + j * 8);
        }
        asm volatile("cp.async.commit_group;" ::: "memory");
    };

    load_stage(0, 0);
    if (NC > 1) load_stage(1, 64);

    float acc[4][8][4] = {};
    // A ldmatrix addressing (x4 per m16 tile)
    const int arow = wm * 64 + (lane & 15);
    const int ac   = lane >> 4;
    const int arx  = arow & 7;
    // B ldmatrix x4 pairs: lanes 0-15 -> nt=2p, lanes 16-31 -> nt=2p+1
    const int brow4 = wn * 64 + ((lane >> 4) << 3) + (lane & 7);
    const int bc4   = (lane >> 3) & 1;
    const int brx4  = brow4 & 7;

#pragma unroll
    for (int c = 0; c < NC; c++) {
        if (c + 1 < NC) asm volatile("cp.async.wait_group 1;" ::: "memory");
        else            asm volatile("cp.async.wait_group 0;" ::: "memory");
        __syncthreads();
        if (c + 2 < NC) load_stage((c + 2) % 3, (c + 2) * 64);

        const uint32_t sA = sb + (c % 3) * STAGE_B, sB = sA + 16384;
#pragma unroll
        for (int ks = 0; ks < 4; ks++) {
            uint32_t af[4][4], bf[8][2];
#pragma unroll
            for (int mt = 0; mt < 4; mt++) {
                int row = arow + mt * 16;
                uint32_t addr = sA + (uint32_t)(row * 128 +
                                (((ks * 2 + ac) ^ arx) << 4));
                ldsm_x4(af[mt], addr);
            }
#pragma unroll
            for (int p = 0; p < 4; p++) {   // each x4 fills bf[2p], bf[2p+1]
                int row = brow4 + p * 16;
                uint32_t addr = sB + (uint32_t)(row * 128 +
                                (((ks * 2 + bc4) ^ brx4) << 4));
                uint32_t r4[4];
                ldsm_x4(r4, addr);
                bf[2 * p][0] = r4[0]; bf[2 * p][1] = r4[1];
                bf[2 * p + 1][0] = r4[2]; bf[2 * p + 1][1] = r4[3];
            }
#pragma unroll
            for (int mt = 0; mt < 4; mt++)
#pragma unroll
                for (int nt = 0; nt < 8; nt++)
                    mma16816(acc[mt][nt], af[mt], bf[nt]);
        }
    }

    const int r0 = blockIdx.y * 128 + wm * 64 + (lane >> 2);
    const int c0 = blockIdx.x * 128 + wn * 64 + (lane & 3) * 2;
#pragma unroll
    for (int mt = 0; mt < 4; mt++) {
#pragma unroll
        for (int nt = 0; nt < 8; nt++) {
            int r = r0 + mt * 16, cc = c0 + nt * 8;
            float b0 = bias[cc], b1 = bias[cc + 1];
            float v00 = acc[mt][nt][0] + b0, v01 = acc[mt][nt][1] + b1;
            float v10 = acc[mt][nt][2] + b0, v11 = acc[mt][nt][3] + b1;
            if constexpr (sizeof(OutT) == 2) {
                *(__half2*)((__half*)C + (size_t)r * N + cc)       = __floats2half2_rn(v00, v01);
                *(__half2*)((__half*)C + (size_t)(r + 8) * N + cc) = __floats2half2_rn(v10, v11);
            } else {
                *(float2*)((float*)C + (size_t)r * N + cc)       = make_float2(v00, v01);
                *(float2*)((float*)C + (size_t)(r + 8) * N + cc) = make_float2(v10, v11);
            }
        }
    }
}

// ---------------------------------------------------------------------------
// Tensor-core attention: one warp per (window, head).
// q/k/v staged to smem: 64 rows x 32 half, row stride 80B (conflict-free).
// S = Q K^T (m16n8k16), masked softmax in registers, O = P V.
// ---------------------------------------------------------------------------
#define AW_BYTES (3 * 64 * 80)   // per-warp smem: q, k, v

__global__ __launch_bounds__(128) void attn_mma(const __half* __restrict__ qkv,
                                                __half* __restrict__ att) {
    extern __shared__ char sm[];
    const int warp = threadIdx.x >> 5, lane = threadIdx.x & 31;
    const int pairid = blockIdx.x * 4 + warp;
    const int win = pairid / HEADS, h = pairid % HEADS;

    char* smp = sm + warp * AW_BYTES;
    const uint32_t base = smem_u32(smp);
    const uint32_t sq = base, sk = base + 5120, sv = base + 10240;

    const __half* qp = qkv + (size_t)win * NTOK * QKVN + h * HD;

    // stage q,k,v (49 rows x 64B each) via cp.async
#pragma unroll
    for (int m = 0; m < 3; m++) {
        const uint32_t dstb = base + m * 5120;
        const __half* src = qp + m * DIM;
        for (int i = lane; i < 196; i += 32) {
            int t = i >> 2, seg = i & 3;
            cp16(dstb + (uint32_t)(t * 80 + seg * 16), src + (size_t)t * QKVN + seg * 8);
        }
    }
    asm volatile("cp.async.commit_group;" ::: "memory");
    // zero pad rows 49..63 of q,k,v
    const float4 z4 = make_float4(0.f, 0.f, 0.f, 0.f);
    for (int i = lane; i < 225; i += 32) {
        int m = i / 75, rem = i % 75;
        int row = 49 + rem / 5, seg = rem % 5;
        *(float4*)(smp + m * 5120 + row * 80 + seg * 16) = z4;
    }
    asm volatile("cp.async.wait_group 0;" ::: "memory");
    __syncwarp();

    const int r   = lane >> 2;
    const int cpr = lane & 3;

    // Hoisted K fragments (B operand of S): kb[nt][ks][2]
    uint32_t kb[7][2][2];
#pragma unroll
    for (int nt = 0; nt < 7; nt++)
#pragma unroll
        for (int ks = 0; ks < 2; ks++) {
            uint32_t addr = sk + (uint32_t)((nt * 8 + (lane & 7)) * 80 +
                            (ks * 2 + ((lane >> 3) & 1)) * 16);
            ldsm_x2(kb[nt][ks], addr);
        }
    // Hoisted V fragments (B operand of O, via trans): vb[ks][nd][2]
    uint32_t vb[4][4][2];
#pragma unroll
    for (int ks = 0; ks < 4; ks++)
#pragma unroll
        for (int nd = 0; nd < 4; nd++) {
            uint32_t addr = sv + (uint32_t)((ks * 16 + (lane & 15)) * 80 + nd * 16);
            ldsm_x2t(vb[ks][nd], addr);
        }

    const float CSC = 0.25506153f;  // (1/sqrt(32)) * log2(e)

#pragma unroll
    for (int mt = 0; mt < 4; mt++) {
        uint32_t qa[2][4];
#pragma unroll
        for (int ks = 0; ks < 2; ks++) {
            uint32_t addr = sq + (uint32_t)((mt * 16 + (lane & 15)) * 80 +
                            (ks * 2 + (lane >> 4)) * 16);
            ldsm_x4(qa[ks], addr);
        }
        float s[7][4] = {};
#pragma unroll
        for (int nt = 0; nt < 7; nt++) {
            mma16816(s[nt], qa[0], kb[nt][0]);
            mma16816(s[nt], qa[1], kb[nt][1]);
        }
        // scale (log2-domain) + mask cols >= 49 (tile nt=6 holds cols 48..55)
#pragma unroll
        for (int nt = 0; nt < 7; nt++)
#pragma unroll
            for (int j = 0; j < 4; j++) s[nt][j] *= CSC;
        if (cpr != 0) { s[6][0] = s[6][1] = s[6][2] = s[6][3] = -1e30f; }
        else          { s[6][1] = s[6][3] = -1e30f; }

        // rowwise max over the 4-lane group
        float mA = -1e30f, mB = -1e30f;
#pragma unroll
        for (int nt = 0; nt < 7; nt++) {
            mA = fmaxf(mA, fmaxf(s[nt][0], s[nt][1]));
            mB = fmaxf(mB, fmaxf(s[nt][2], s[nt][3]));
        }
        mA = fmaxf(mA, __shfl_xor_sync(0xffffffffu, mA, 1));
        mA = fmaxf(mA, __shfl_xor_sync(0xffffffffu, mA, 2));
        mB = fmaxf(mB, __shfl_xor_sync(0xffffffffu, mB, 1));
        mB = fmaxf(mB, __shfl_xor_sync(0xffffffffu, mB, 2));

        float sumA = 0.f, sumB = 0.f;
#pragma unroll
        for (int nt = 0; nt < 7; nt++) {
            s[nt][0] = ex2(s[nt][0] - mA);
            s[nt][1] = ex2(s[nt][1] - mA);
            s[nt][2] = ex2(s[nt][2] - mB);
            s[nt][3] = ex2(s[nt][3] - mB);
            sumA += s[nt][0] + s[nt][1];
            sumB += s[nt][2] + s[nt][3];
        }
        sumA += __shfl_xor_sync(0xffffffffu, sumA, 1);
        sumA += __shfl_xor_sync(0xffffffffu, sumA, 2);
        sumB += __shfl_xor_sync(0xffffffffu, sumB, 1);
        sumB += __shfl_xor_sync(0xffffffffu, sumB, 2);
        const float invA = 1.0f / sumA, invB = 1.0f / sumB;

        // convert P to A-operand fragments: pa[ks][4]
        uint32_t pa[4][4];
#pragma unroll
        for (int ks = 0; ks < 4; ks++) {
            int nt0 = 2 * ks, nt1 = 2 * ks + 1;
            pa[ks][0] = pack_h2(s[nt0][0] * invA, s[nt0][1] * invA);
            pa[ks][1] = pack_h2(s[nt0][2] * invB, s[nt0][3] * invB);
            if (nt1 < 7) {
                pa[ks][2] = pack_h2(s[nt1][0] * invA, s[nt1][1] * invA);
                pa[ks][3] = pack_h2(s[nt1][2] * invB, s[nt1][3] * invB);
            } else {
                pa[ks][2] = 0u; pa[ks][3] = 0u;
            }
        }

        float o[4][4] = {};
#pragma unroll
        for (int ks = 0; ks < 4; ks++)
#pragma unroll
            for (int nd = 0; nd < 4; nd++)
                mma16816(o[nd], pa[ks], vb[ks][nd]);

        // store O rows (mt*16 + r) and (+8), cols nd*8 + cpr*2
        const int rowA = mt * 16 + r;
        const int rowB = rowA + 8;
#pragma unroll
        for (int nd = 0; nd < 4; nd++) {
            int col = h * HD + nd * 8 + cpr * 2;
            if (rowA < NTOK)
                *(__half2*)(att + (size_t)(win * NTOK + rowA) * DIM + col) =
                    __floats2half2_rn(o[nd][0], o[nd][1]);
            if (rowB < NTOK)
                *(__half2*)(att + (size_t)(win * NTOK + rowB) * DIM + col) =
                    __floats2half2_rn(o[nd][2], o[nd][3]);
        }
    }
}

// ---------------------------------------------------------------------------
extern "C" void kernel_launch(void* const* d_in, const int* in_sizes, int n_in,
                              void* d_out, int out_size) {
    const float* x     = (const float*)d_in[0];
    const float* Wqkv  = (const float*)d_in[1];
    const float* bqkv  = (const float*)d_in[2];
    const float* Wproj = (const float*)d_in[3];
    const float* bproj = (const float*)d_in[4];
    float* out = (float*)d_out;

    __half *xwh, *qkvh, *atth, *wt, *wtp;
    float *po;
    cudaGetSymbolAddress((void**)&xwh,  g_xwh);
    cudaGetSymbolAddress((void**)&qkvh, g_qkvh);
    cudaGetSymbolAddress((void**)&atth, g_atth);
    cudaGetSymbolAddress((void**)&po,   g_out);
    cudaGetSymbolAddress((void**)&wt,   g_wt);
    cudaGetSymbolAddress((void**)&wtp,  g_wtp);

    const int gemm_smem = 3 * STAGE_B + 1024;   // 3-stage pipeline
    cudaFuncSetAttribute((const void*)hgemm<__half, DIM>,
                         cudaFuncAttributeMaxDynamicSharedMemorySize, gemm_smem);
    cudaFuncSetAttribute((const void*)hgemm<float, DIM>,
                         cudaFuncAttributeMaxDynamicSharedMemorySize, gemm_smem);
    const int attn_smem = 4 * AW_BYTES;
    cudaFuncSetAttribute(attn_mma, cudaFuncAttributeMaxDynamicSharedMemorySize, attn_smem);

    transpose_w<<<dim3(QKVN / 32, DIM / 32), dim3(32, 8)>>>(Wqkv, wt, DIM, QKVN);
    transpose_w<<<dim3(DIM / 32, DIM / 32), dim3(32, 8)>>>(Wproj, wtp, DIM, DIM);
    gather_win<<<dim3(6, HW, BB), 256>>>(x, xwh);
    hgemm<__half, DIM><<<dim3(QKVN / 128, ROWS / 128), 128, gemm_smem>>>(
        xwh, wt, bqkv, qkvh, ROWS, QKVN);
    attn_mma<<<NWIN * HEADS / 4, 128, attn_smem>>>(qkvh, atth);
    hgemm<float, DIM><<<dim3(DIM / 128, ROWS / 128), 128, gemm_smem>>>(
        atth, wtp, bproj, po, ROWS, DIM);
    scatter_win<<<dim3(6, HW, BB), 256>>>(po, out);
}